// round 8
// baseline (speedup 1.0000x reference)
#include <cuda_runtime.h>

#define BN 128
#define NNq 512
#define PDq 128
#define SDq 256
#define FDq 256
#define NITERS 30

__device__ float g_Sp[BN * NNq * PDq];
__device__ float g_Fp[BN * NNq * PDq];
__device__ float g_K[(size_t)BN * NNq * NNq];
__device__ float g_u[BN * NNq];
__device__ float g_v[BN * NNq];

__device__ __forceinline__ unsigned long long pack2(float x, float y) {
    unsigned long long r;
    asm("mov.b64 %0, {%1, %2};" : "=l"(r) : "f"(x), "f"(y));
    return r;
}
__device__ __forceinline__ void fma2(unsigned long long& d,
                                     unsigned long long a, unsigned long long b) {
    asm("fma.rn.f32x2 %0, %1, %2, %0;" : "+l"(d) : "l"(a), "l"(b));
}
__device__ __forceinline__ float2 unpack2(unsigned long long v) {
    float lo, hi;
    asm("mov.b64 {%0, %1}, %2;" : "=f"(lo), "=f"(hi) : "l"(v));
    return make_float2(lo, hi);
}

// ============================================================
// K1: H = X@W + b ; LayerNorm ; L2norm -> g_Sp/g_Fp
// X:[65536,256] W:[256,128]. CTA: 64 rows x 128 cols, 256 thr.
// ============================================================
__global__ __launch_bounds__(256) void proj_kernel(
    const float* __restrict__ X, const float* __restrict__ W,
    const float* __restrict__ bias, const float* __restrict__ gamma,
    const float* __restrict__ beta, int which)
{
    __shared__ float buf[8192];
    float* Xs = buf;                 // [64][33]
    float* Ws = buf + 64 * 33;       // [32][128]
    float* outp = which ? g_Fp : g_Sp;
    int t = threadIdx.x, tx = t & 15, ty = t >> 4;
    int row0 = blockIdx.x * 64;

    unsigned long long acc2[4][4];
#pragma unroll
    for (int i = 0; i < 4; i++)
#pragma unroll
        for (int j = 0; j < 4; j++) acc2[i][j] = 0ull;

    for (int kc = 0; kc < SDq; kc += 32) {
#pragma unroll
        for (int l = 0; l < 2; l++) {
            int r = (t >> 3) + 32 * l, c4 = (t & 7) * 4;
            float4 v = *reinterpret_cast<const float4*>(X + (size_t)(row0 + r) * SDq + kc + c4);
            Xs[r * 33 + c4] = v.x; Xs[r * 33 + c4 + 1] = v.y;
            Xs[r * 33 + c4 + 2] = v.z; Xs[r * 33 + c4 + 3] = v.w;
        }
#pragma unroll
        for (int l = 0; l < 4; l++) {
            int r = (t >> 5) + 8 * l, c4 = (t & 31) * 4;
            *reinterpret_cast<float4*>(Ws + r * 128 + c4) =
                *reinterpret_cast<const float4*>(W + (size_t)(kc + r) * PDq + c4);
        }
        __syncthreads();
#pragma unroll
        for (int k = 0; k < 32; k++) {
            unsigned long long a2[4], w2[4];
#pragma unroll
            for (int i = 0; i < 4; i++) {
                float a = Xs[(ty * 4 + i) * 33 + k];
                a2[i] = pack2(a, a);
            }
#pragma unroll
            for (int j = 0; j < 4; j++)
                w2[j] = *reinterpret_cast<const unsigned long long*>(Ws + k * 128 + tx * 8 + 2 * j);
#pragma unroll
            for (int i = 0; i < 4; i++)
#pragma unroll
                for (int j = 0; j < 4; j++) fma2(acc2[i][j], a2[i], w2[j]);
        }
        __syncthreads();
    }

    float* Hs = buf;  // reuse as [64][128]
#pragma unroll
    for (int i = 0; i < 4; i++) {
        int r = ty * 4 + i;
#pragma unroll
        for (int j = 0; j < 4; j++) {
            float2 p = unpack2(acc2[i][j]);
            int c = tx * 8 + 2 * j;
            Hs[r * 128 + c] = p.x + __ldg(bias + c);
            Hs[r * 128 + c + 1] = p.y + __ldg(bias + c + 1);
        }
    }
    __syncthreads();

    int w = t >> 5, lane = t & 31;
    for (int q = 0; q < 8; q++) {
        int r = w * 8 + q;
        float h[4];
#pragma unroll
        for (int j = 0; j < 4; j++) h[j] = Hs[r * 128 + lane + 32 * j];
        float s = h[0] + h[1] + h[2] + h[3];
#pragma unroll
        for (int o = 16; o; o >>= 1) s += __shfl_xor_sync(0xffffffffu, s, o);
        float mu = s * (1.0f / 128.0f);
        float vs = 0.f;
#pragma unroll
        for (int j = 0; j < 4; j++) { float d = h[j] - mu; vs += d * d; }
#pragma unroll
        for (int o = 16; o; o >>= 1) vs += __shfl_xor_sync(0xffffffffu, vs, o);
        float rstd = rsqrtf(vs * (1.0f / 128.0f) + 1e-5f);
        float y[4]; float ss = 0.f;
#pragma unroll
        for (int j = 0; j < 4; j++) {
            int c = lane + 32 * j;
            y[j] = (h[j] - mu) * rstd * __ldg(gamma + c) + __ldg(beta + c);
            ss += y[j] * y[j];
        }
#pragma unroll
        for (int o = 16; o; o >>= 1) ss += __shfl_xor_sync(0xffffffffu, ss, o);
        float inv = 1.0f / fmaxf(sqrtf(ss), 1e-12f);
        size_t ob = (size_t)(row0 + r) * PDq;
#pragma unroll
        for (int j = 0; j < 4; j++) outp[ob + lane + 32 * j] = y[j] * inv;
    }
}

// ============================================================
// K2: cos = Sp@Fp^T ; K = exp(-10*clip(1-cos,0,2)) -> g_K
// grid (8,8,128), 64x64 tile, 256 thr, 4x4 per thread.
// ============================================================
__global__ __launch_bounds__(256) void cosk_kernel()
{
    __shared__ float As[64 * 65];
    __shared__ float Bs[64 * 65];
    int t = threadIdx.x, tx = t & 15, ty = t >> 4;
    int jt = blockIdx.x, it = blockIdx.y, b = blockIdx.z;
    const float* Ab = g_Sp + ((size_t)b * NNq + it * 64) * PDq;
    const float* Bb = g_Fp + ((size_t)b * NNq + jt * 64) * PDq;

    float acc[4][4];
#pragma unroll
    for (int i = 0; i < 4; i++)
#pragma unroll
        for (int j = 0; j < 4; j++) acc[i][j] = 0.f;

    for (int kc = 0; kc < PDq; kc += 64) {
#pragma unroll
        for (int l = 0; l < 4; l++) {
            int r = (t >> 4) + 16 * l, c4 = (t & 15) * 4;
            float4 va = *reinterpret_cast<const float4*>(Ab + (size_t)r * PDq + kc + c4);
            As[r * 65 + c4] = va.x; As[r * 65 + c4 + 1] = va.y;
            As[r * 65 + c4 + 2] = va.z; As[r * 65 + c4 + 3] = va.w;
            float4 vb = *reinterpret_cast<const float4*>(Bb + (size_t)r * PDq + kc + c4);
            Bs[r * 65 + c4] = vb.x; Bs[r * 65 + c4 + 1] = vb.y;
            Bs[r * 65 + c4 + 2] = vb.z; Bs[r * 65 + c4 + 3] = vb.w;
        }
        __syncthreads();
#pragma unroll 8
        for (int k = 0; k < 64; k++) {
            float a[4], bb[4];
#pragma unroll
            for (int i = 0; i < 4; i++) a[i] = As[(ty * 4 + i) * 65 + k];
#pragma unroll
            for (int j = 0; j < 4; j++) bb[j] = Bs[(tx * 4 + j) * 65 + k];
#pragma unroll
            for (int i = 0; i < 4; i++)
#pragma unroll
                for (int j = 0; j < 4; j++) acc[i][j] += a[i] * bb[j];
        }
        __syncthreads();
    }
#pragma unroll
    for (int i = 0; i < 4; i++) {
        float4 o;
        o.x = expf(-10.0f * fminf(fmaxf(1.0f - acc[i][0], 0.f), 2.f));
        o.y = expf(-10.0f * fminf(fmaxf(1.0f - acc[i][1], 0.f), 2.f));
        o.z = expf(-10.0f * fminf(fmaxf(1.0f - acc[i][2], 0.f), 2.f));
        o.w = expf(-10.0f * fminf(fmaxf(1.0f - acc[i][3], 0.f), 2.f));
        size_t idx = ((size_t)b * NNq + it * 64 + ty * 4 + i) * NNq + jt * 64 + tx * 4;
        *reinterpret_cast<float4*>(g_K + idx) = o;
    }
}

// ============================================================
// K3: Sinkhorn 30 iters. 1 CTA / batch, 512 thr (16 warps).
// One pass over K per iter: row in regs serves Kv AND K^T u.
// ============================================================
__global__ __launch_bounds__(512) void sinkhorn_kernel()
{
    __shared__ float vs[512];
    __shared__ float us[512];
    __shared__ float part[16 * 512];
    int t = threadIdx.x, w = t >> 5, l = t & 31, b = blockIdx.x;
    const float4* Kb = reinterpret_cast<const float4*>(g_K + (size_t)b * NNq * NNq);

    vs[t] = 1.0f;
    __syncthreads();
    const float rr = 1.0f / 512.0f;

    for (int iter = 0; iter < NITERS; ++iter) {
        float acc[4][4];
#pragma unroll
        for (int g = 0; g < 4; g++)
#pragma unroll
            for (int c = 0; c < 4; c++) acc[g][c] = 0.f;

        for (int row = w * 32; row < w * 32 + 32; ++row) {
            const float4* Kr = Kb + (size_t)row * 128;
            float4 kf[4]; float s = 0.f;
#pragma unroll
            for (int g = 0; g < 4; g++) {
                kf[g] = Kr[l + 32 * g];
                float4 vv = *reinterpret_cast<const float4*>(vs + l * 4 + 128 * g);
                s += kf[g].x * vv.x + kf[g].y * vv.y + kf[g].z * vv.z + kf[g].w * vv.w;
            }
#pragma unroll
            for (int o = 16; o; o >>= 1) s += __shfl_xor_sync(0xffffffffu, s, o);
            float u = rr / (s + 1e-8f);          // unclipped u feeds K^T u (matches ref)
            if (l == 0) us[row] = u;
#pragma unroll
            for (int g = 0; g < 4; g++) {
                acc[g][0] += u * kf[g].x; acc[g][1] += u * kf[g].y;
                acc[g][2] += u * kf[g].z; acc[g][3] += u * kf[g].w;
            }
        }
#pragma unroll
        for (int g = 0; g < 4; g++)
            *reinterpret_cast<float4*>(part + w * 512 + l * 4 + 128 * g) =
                make_float4(acc[g][0], acc[g][1], acc[g][2], acc[g][3]);
        __syncthreads();

        float kt = 0.f;
#pragma unroll
        for (int ww = 0; ww < 16; ++ww) kt += part[ww * 512 + t];
        float v = rr / (kt + 1e-8f);
        vs[t] = fminf(fmaxf(v, 1e-8f), 1e8f);   // clipped v for next iter (matches ref)
        __syncthreads();
    }
    g_u[b * NNq + t] = fminf(fmaxf(us[t], 1e-8f), 1e8f);
    g_v[b * NNq + t] = vs[t];
}

// ============================================================
// K4: P = u*K*v (fused into K load) ; Ft = u * (K @ (v*F))
// grid (8 row-tiles, 128 batches), 256 thr. CTA: 64 rows x 256 d.
// Per thread: 4 rows x 16 d (interleaved d: cols tx*4 + 64*jj).
// ============================================================
__global__ __launch_bounds__(256) void ftilde_kernel(
    const float* __restrict__ F, float* __restrict__ outP, float* __restrict__ outFt)
{
    __shared__ float As[64 * 33];    // K tile [row][k]
    __shared__ float Bs[32 * 260];   // G tile [k][d], G = v (*) F
    int t = threadIdx.x, tx = t & 15, ty = t >> 4;
    int it = blockIdx.x, b = blockIdx.y;
    const float* ub = g_u + b * NNq;
    const float* vb = g_v + b * NNq;

    float acc[4][16];
#pragma unroll
    for (int i = 0; i < 4; i++)
#pragma unroll
        for (int j = 0; j < 16; j++) acc[i][j] = 0.f;

    for (int kc = 0; kc < NNq; kc += 32) {
        // K tile + fused P write (each K strip owned by exactly one CTA)
#pragma unroll
        for (int l = 0; l < 2; l++) {
            int r = t >> 2, col = (t & 3) * 4 + 16 * l;
            size_t gidx = ((size_t)b * NNq + it * 64 + r) * NNq + kc + col;
            float4 kv = *reinterpret_cast<const float4*>(g_K + gidx);
            As[r * 33 + col] = kv.x; As[r * 33 + col + 1] = kv.y;
            As[r * 33 + col + 2] = kv.z; As[r * 33 + col + 3] = kv.w;
            float ui = __ldg(ub + it * 64 + r);
            float4 v4 = *reinterpret_cast<const float4*>(vb + kc + col);
            float4 p;
            p.x = kv.x * ui * v4.x; p.y = kv.y * ui * v4.y;
            p.z = kv.z * ui * v4.z; p.w = kv.w * ui * v4.w;
            *reinterpret_cast<float4*>(outP + gidx) = p;
        }
        // G tile: 32 k-rows x 256 d
#pragma unroll
        for (int jj = 0; jj < 8; jj++) {
            int r = t >> 3, col = (t & 7) * 4 + 32 * jj;
            float vsc = __ldg(vb + kc + r);
            float4 f4 = *reinterpret_cast<const float4*>(
                F + ((size_t)b * NNq + kc + r) * FDq + col);
            f4.x *= vsc; f4.y *= vsc; f4.z *= vsc; f4.w *= vsc;
            *reinterpret_cast<float4*>(Bs + r * 260 + col) = f4;
        }
        __syncthreads();
#pragma unroll 4
        for (int k = 0; k < 32; k++) {
            float a[4];
#pragma unroll
            for (int i = 0; i < 4; i++) a[i] = As[(ty * 4 + i) * 33 + k];
#pragma unroll
            for (int jj = 0; jj < 4; jj++) {
                float4 b4 = *reinterpret_cast<const float4*>(Bs + k * 260 + tx * 4 + 64 * jj);
#pragma unroll
                for (int i = 0; i < 4; i++) {
                    acc[i][jj * 4 + 0] += a[i] * b4.x;
                    acc[i][jj * 4 + 1] += a[i] * b4.y;
                    acc[i][jj * 4 + 2] += a[i] * b4.z;
                    acc[i][jj * 4 + 3] += a[i] * b4.w;
                }
            }
        }
        __syncthreads();
    }
#pragma unroll
    for (int i = 0; i < 4; i++) {
        int row = it * 64 + ty * 4 + i;
        float ui = __ldg(ub + row);
#pragma unroll
        for (int jj = 0; jj < 4; jj++) {
            float4 o;
            o.x = ui * acc[i][jj * 4 + 0]; o.y = ui * acc[i][jj * 4 + 1];
            o.z = ui * acc[i][jj * 4 + 2]; o.w = ui * acc[i][jj * 4 + 3];
            *reinterpret_cast<float4*>(
                outFt + ((size_t)b * NNq + row) * FDq + tx * 4 + 64 * jj) = o;
        }
    }
}

// ============================================================
extern "C" void kernel_launch(void* const* d_in, const int* in_sizes, int n_in,
                              void* d_out, int out_size)
{
    const float* S      = (const float*)d_in[0];
    const float* F      = (const float*)d_in[1];
    const float* W_s    = (const float*)d_in[2];
    const float* b_s    = (const float*)d_in[3];
    const float* g_s    = (const float*)d_in[4];
    const float* beta_s = (const float*)d_in[5];
    const float* W_f    = (const float*)d_in[6];
    const float* b_f    = (const float*)d_in[7];
    const float* g_f    = (const float*)d_in[8];
    const float* beta_f = (const float*)d_in[9];

    float* outP  = (float*)d_out;                               // [B,N,N]
    float* outFt = (float*)d_out + (size_t)BN * NNq * NNq;      // [B,N,FD]

    proj_kernel<<<(BN * NNq) / 64, 256>>>(S, W_s, b_s, g_s, beta_s, 0);
    proj_kernel<<<(BN * NNq) / 64, 256>>>(F, W_f, b_f, g_f, beta_f, 1);

    dim3 gcos(NNq / 64, NNq / 64, BN);
    cosk_kernel<<<gcos, 256>>>();

    sinkhorn_kernel<<<BN, 512>>>();

    dim3 gft(NNq / 64, BN);
    ftilde_kernel<<<gft, 256>>>(F, outP, outFt);
}

// round 9
// speedup vs baseline: 1.8480x; 1.8480x over previous
#include <cuda_runtime.h>
#include <cuda_bf16.h>

#define BN 128
#define NNq 512
#define PDq 128
#define SDq 256
#define FDq 256
#define NITERS 30

__device__ float g_Sp[BN * NNq * PDq];
__device__ float g_Fp[BN * NNq * PDq];
__device__ float g_K[(size_t)BN * NNq * NNq];
__device__ __nv_bfloat16 g_Kh[(size_t)BN * NNq * NNq];
__device__ float g_u[BN * NNq];
__device__ float g_v[BN * NNq];

__device__ __forceinline__ unsigned long long pack2(float x, float y) {
    unsigned long long r;
    asm("mov.b64 %0, {%1, %2};" : "=l"(r) : "f"(x), "f"(y));
    return r;
}
__device__ __forceinline__ void fma2(unsigned long long& d,
                                     unsigned long long a, unsigned long long b) {
    asm("fma.rn.f32x2 %0, %1, %2, %0;" : "+l"(d) : "l"(a), "l"(b));
}
__device__ __forceinline__ float2 unpack2(unsigned long long v) {
    float lo, hi;
    asm("mov.b64 {%0, %1}, %2;" : "=f"(lo), "=f"(hi) : "l"(v));
    return make_float2(lo, hi);
}

// ============================================================
// K1: H = X@W + b ; LayerNorm ; L2norm -> g_Sp/g_Fp
// ============================================================
__global__ __launch_bounds__(256) void proj_kernel(
    const float* __restrict__ X, const float* __restrict__ W,
    const float* __restrict__ bias, const float* __restrict__ gamma,
    const float* __restrict__ beta, int which)
{
    __shared__ float buf[8192];
    float* Xs = buf;                 // [64][33]
    float* Ws = buf + 64 * 33;       // [32][128]
    float* outp = which ? g_Fp : g_Sp;
    int t = threadIdx.x, tx = t & 15, ty = t >> 4;
    int row0 = blockIdx.x * 64;

    unsigned long long acc2[4][4];
#pragma unroll
    for (int i = 0; i < 4; i++)
#pragma unroll
        for (int j = 0; j < 4; j++) acc2[i][j] = 0ull;

    for (int kc = 0; kc < SDq; kc += 32) {
#pragma unroll
        for (int l = 0; l < 2; l++) {
            int r = (t >> 3) + 32 * l, c4 = (t & 7) * 4;
            float4 v = *reinterpret_cast<const float4*>(X + (size_t)(row0 + r) * SDq + kc + c4);
            Xs[r * 33 + c4] = v.x; Xs[r * 33 + c4 + 1] = v.y;
            Xs[r * 33 + c4 + 2] = v.z; Xs[r * 33 + c4 + 3] = v.w;
        }
#pragma unroll
        for (int l = 0; l < 4; l++) {
            int r = (t >> 5) + 8 * l, c4 = (t & 31) * 4;
            *reinterpret_cast<float4*>(Ws + r * 128 + c4) =
                *reinterpret_cast<const float4*>(W + (size_t)(kc + r) * PDq + c4);
        }
        __syncthreads();
#pragma unroll
        for (int k = 0; k < 32; k++) {
            unsigned long long a2[4], w2[4];
#pragma unroll
            for (int i = 0; i < 4; i++) {
                float a = Xs[(ty * 4 + i) * 33 + k];
                a2[i] = pack2(a, a);
            }
#pragma unroll
            for (int j = 0; j < 4; j++)
                w2[j] = *reinterpret_cast<const unsigned long long*>(Ws + k * 128 + tx * 8 + 2 * j);
#pragma unroll
            for (int i = 0; i < 4; i++)
#pragma unroll
                for (int j = 0; j < 4; j++) fma2(acc2[i][j], a2[i], w2[j]);
        }
        __syncthreads();
    }

    float* Hs = buf;  // reuse as [64][128]
#pragma unroll
    for (int i = 0; i < 4; i++) {
        int r = ty * 4 + i;
#pragma unroll
        for (int j = 0; j < 4; j++) {
            float2 p = unpack2(acc2[i][j]);
            int c = tx * 8 + 2 * j;
            Hs[r * 128 + c] = p.x + __ldg(bias + c);
            Hs[r * 128 + c + 1] = p.y + __ldg(bias + c + 1);
        }
    }
    __syncthreads();

    int w = t >> 5, lane = t & 31;
    for (int q = 0; q < 8; q++) {
        int r = w * 8 + q;
        float h[4];
#pragma unroll
        for (int j = 0; j < 4; j++) h[j] = Hs[r * 128 + lane + 32 * j];
        float s = h[0] + h[1] + h[2] + h[3];
#pragma unroll
        for (int o = 16; o; o >>= 1) s += __shfl_xor_sync(0xffffffffu, s, o);
        float mu = s * (1.0f / 128.0f);
        float vsm = 0.f;
#pragma unroll
        for (int j = 0; j < 4; j++) { float d = h[j] - mu; vsm += d * d; }
#pragma unroll
        for (int o = 16; o; o >>= 1) vsm += __shfl_xor_sync(0xffffffffu, vsm, o);
        float rstd = rsqrtf(vsm * (1.0f / 128.0f) + 1e-5f);
        float y[4]; float ss = 0.f;
#pragma unroll
        for (int j = 0; j < 4; j++) {
            int c = lane + 32 * j;
            y[j] = (h[j] - mu) * rstd * __ldg(gamma + c) + __ldg(beta + c);
            ss += y[j] * y[j];
        }
#pragma unroll
        for (int o = 16; o; o >>= 1) ss += __shfl_xor_sync(0xffffffffu, ss, o);
        float inv = 1.0f / fmaxf(sqrtf(ss), 1e-12f);
        size_t ob = (size_t)(row0 + r) * PDq;
#pragma unroll
        for (int j = 0; j < 4; j++) outp[ob + lane + 32 * j] = y[j] * inv;
    }
}

// ============================================================
// K2: cos = Sp@Fp^T ; K = exp(-10*clip(1-cos,0,2)) -> g_K (fp32) + g_Kh (bf16 rn)
// ============================================================
__global__ __launch_bounds__(256) void cosk_kernel()
{
    __shared__ float As[64 * 65];
    __shared__ float Bs[64 * 65];
    int t = threadIdx.x, tx = t & 15, ty = t >> 4;
    int jt = blockIdx.x, it = blockIdx.y, b = blockIdx.z;
    const float* Ab = g_Sp + ((size_t)b * NNq + it * 64) * PDq;
    const float* Bb = g_Fp + ((size_t)b * NNq + jt * 64) * PDq;

    float acc[4][4];
#pragma unroll
    for (int i = 0; i < 4; i++)
#pragma unroll
        for (int j = 0; j < 4; j++) acc[i][j] = 0.f;

    for (int kc = 0; kc < PDq; kc += 64) {
#pragma unroll
        for (int l = 0; l < 4; l++) {
            int r = (t >> 4) + 16 * l, c4 = (t & 15) * 4;
            float4 va = *reinterpret_cast<const float4*>(Ab + (size_t)r * PDq + kc + c4);
            As[r * 65 + c4] = va.x; As[r * 65 + c4 + 1] = va.y;
            As[r * 65 + c4 + 2] = va.z; As[r * 65 + c4 + 3] = va.w;
            float4 vb = *reinterpret_cast<const float4*>(Bb + (size_t)r * PDq + kc + c4);
            Bs[r * 65 + c4] = vb.x; Bs[r * 65 + c4 + 1] = vb.y;
            Bs[r * 65 + c4 + 2] = vb.z; Bs[r * 65 + c4 + 3] = vb.w;
        }
        __syncthreads();
#pragma unroll 8
        for (int k = 0; k < 64; k++) {
            float a[4], bb[4];
#pragma unroll
            for (int i = 0; i < 4; i++) a[i] = As[(ty * 4 + i) * 65 + k];
#pragma unroll
            for (int j = 0; j < 4; j++) bb[j] = Bs[(tx * 4 + j) * 65 + k];
#pragma unroll
            for (int i = 0; i < 4; i++)
#pragma unroll
                for (int j = 0; j < 4; j++) acc[i][j] += a[i] * bb[j];
        }
        __syncthreads();
    }
#pragma unroll
    for (int i = 0; i < 4; i++) {
        float4 o;
        o.x = __expf(-10.0f * fminf(fmaxf(1.0f - acc[i][0], 0.f), 2.f));
        o.y = __expf(-10.0f * fminf(fmaxf(1.0f - acc[i][1], 0.f), 2.f));
        o.z = __expf(-10.0f * fminf(fmaxf(1.0f - acc[i][2], 0.f), 2.f));
        o.w = __expf(-10.0f * fminf(fmaxf(1.0f - acc[i][3], 0.f), 2.f));
        size_t idx = ((size_t)b * NNq + it * 64 + ty * 4 + i) * NNq + jt * 64 + tx * 4;
        *reinterpret_cast<float4*>(g_K + idx) = o;
        __nv_bfloat162 h0 = __floats2bfloat162_rn(o.x, o.y);
        __nv_bfloat162 h1 = __floats2bfloat162_rn(o.z, o.w);
        uint2 hh;
        hh.x = *reinterpret_cast<unsigned int*>(&h0);
        hh.y = *reinterpret_cast<unsigned int*>(&h1);
        *reinterpret_cast<uint2*>(g_Kh + idx) = hh;
    }
}

// ============================================================
// K3: Sinkhorn 30 iters on bf16 K (L2-resident: 67MB < 126MB L2).
// 1 CTA/batch, 512 thr. Lane l owns 16 cols: {8l..8l+7, 256+8l..256+8l+7}.
// Single pass per iter: row in regs serves Kv AND K^T u.
// ============================================================
__global__ __launch_bounds__(512) void sinkhorn_kernel()
{
    __shared__ float vs[512];
    __shared__ float us[512];
    __shared__ float part[16 * 512];
    int t = threadIdx.x, w = t >> 5, l = t & 31, b = blockIdx.x;
    const uint4* Kb = reinterpret_cast<const uint4*>(g_Kh + (size_t)b * NNq * NNq);

    vs[t] = 1.0f;
    __syncthreads();
    const float rr = 1.0f / 512.0f;

    for (int iter = 0; iter < NITERS; ++iter) {
        float acc[16];
#pragma unroll
        for (int i = 0; i < 16; i++) acc[i] = 0.f;

        // preload v for this lane's 16 owned columns
        float va[16];
#pragma unroll
        for (int h = 0; h < 2; h++) {
            float4 v0 = *reinterpret_cast<const float4*>(vs + 256 * h + 8 * l);
            float4 v1 = *reinterpret_cast<const float4*>(vs + 256 * h + 8 * l + 4);
            va[h * 8 + 0] = v0.x; va[h * 8 + 1] = v0.y;
            va[h * 8 + 2] = v0.z; va[h * 8 + 3] = v0.w;
            va[h * 8 + 4] = v1.x; va[h * 8 + 5] = v1.y;
            va[h * 8 + 6] = v1.z; va[h * 8 + 7] = v1.w;
        }

#pragma unroll 4
        for (int row = w * 32; row < w * 32 + 32; ++row) {
            uint4 k0 = Kb[(size_t)row * 64 + l];
            uint4 k1 = Kb[(size_t)row * 64 + 32 + l];
            float kf[16];
            kf[0]  = __uint_as_float(k0.x << 16);
            kf[1]  = __uint_as_float(k0.x & 0xffff0000u);
            kf[2]  = __uint_as_float(k0.y << 16);
            kf[3]  = __uint_as_float(k0.y & 0xffff0000u);
            kf[4]  = __uint_as_float(k0.z << 16);
            kf[5]  = __uint_as_float(k0.z & 0xffff0000u);
            kf[6]  = __uint_as_float(k0.w << 16);
            kf[7]  = __uint_as_float(k0.w & 0xffff0000u);
            kf[8]  = __uint_as_float(k1.x << 16);
            kf[9]  = __uint_as_float(k1.x & 0xffff0000u);
            kf[10] = __uint_as_float(k1.y << 16);
            kf[11] = __uint_as_float(k1.y & 0xffff0000u);
            kf[12] = __uint_as_float(k1.z << 16);
            kf[13] = __uint_as_float(k1.z & 0xffff0000u);
            kf[14] = __uint_as_float(k1.w << 16);
            kf[15] = __uint_as_float(k1.w & 0xffff0000u);

            float s = 0.f;
#pragma unroll
            for (int i = 0; i < 16; i++) s += kf[i] * va[i];
#pragma unroll
            for (int o = 16; o; o >>= 1) s += __shfl_xor_sync(0xffffffffu, s, o);
            float u = rr / (s + 1e-8f);          // unclipped u feeds K^T u (matches ref)
            if (l == 0) us[row] = u;
#pragma unroll
            for (int i = 0; i < 16; i++) acc[i] += u * kf[i];
        }

        // write per-warp partials for owned columns
#pragma unroll
        for (int h = 0; h < 2; h++) {
            *reinterpret_cast<float4*>(part + w * 512 + 256 * h + 8 * l) =
                make_float4(acc[h * 8 + 0], acc[h * 8 + 1], acc[h * 8 + 2], acc[h * 8 + 3]);
            *reinterpret_cast<float4*>(part + w * 512 + 256 * h + 8 * l + 4) =
                make_float4(acc[h * 8 + 4], acc[h * 8 + 5], acc[h * 8 + 6], acc[h * 8 + 7]);
        }
        __syncthreads();

        float kt = 0.f;
#pragma unroll
        for (int ww = 0; ww < 16; ++ww) kt += part[ww * 512 + t];
        float v = rr / (kt + 1e-8f);
        vs[t] = fminf(fmaxf(v, 1e-8f), 1e8f);   // clipped v for next iter (matches ref)
        __syncthreads();
    }
    g_u[b * NNq + t] = fminf(fmaxf(us[t], 1e-8f), 1e8f);
    g_v[b * NNq + t] = vs[t];
}

// ============================================================
// K4: P = u*K*v (fused into K load) ; Ft = u * (K @ (v*F))
// grid (8 row-tiles, 128 batches), 256 thr. CTA: 64 rows x 256 d.
// Inner loop uses packed fma.rn.f32x2 (Bs is k-major -> d pairs contiguous).
// ============================================================
__global__ __launch_bounds__(256) void ftilde_kernel(
    const float* __restrict__ F, float* __restrict__ outP, float* __restrict__ outFt)
{
    __shared__ float As[64 * 33];    // K tile [row][k]
    __shared__ float Bs[32 * 260];   // G tile [k][d], G = v (*) F
    int t = threadIdx.x, tx = t & 15, ty = t >> 4;
    int it = blockIdx.x, b = blockIdx.y;
    const float* ub = g_u + b * NNq;
    const float* vb = g_v + b * NNq;

    unsigned long long acc2[4][8];
#pragma unroll
    for (int i = 0; i < 4; i++)
#pragma unroll
        for (int j = 0; j < 8; j++) acc2[i][j] = 0ull;

    for (int kc = 0; kc < NNq; kc += 32) {
        // K tile + fused P write (each K strip owned by exactly one CTA)
#pragma unroll
        for (int l = 0; l < 2; l++) {
            int r = t >> 2, col = (t & 3) * 4 + 16 * l;
            size_t gidx = ((size_t)b * NNq + it * 64 + r) * NNq + kc + col;
            float4 kv = *reinterpret_cast<const float4*>(g_K + gidx);
            As[r * 33 + col] = kv.x; As[r * 33 + col + 1] = kv.y;
            As[r * 33 + col + 2] = kv.z; As[r * 33 + col + 3] = kv.w;
            float ui = __ldg(ub + it * 64 + r);
            float4 v4 = *reinterpret_cast<const float4*>(vb + kc + col);
            float4 p;
            p.x = kv.x * ui * v4.x; p.y = kv.y * ui * v4.y;
            p.z = kv.z * ui * v4.z; p.w = kv.w * ui * v4.w;
            *reinterpret_cast<float4*>(outP + gidx) = p;
        }
        // G tile: 32 k-rows x 256 d
#pragma unroll
        for (int jj = 0; jj < 8; jj++) {
            int r = t >> 3, col = (t & 7) * 4 + 32 * jj;
            float vsc = __ldg(vb + kc + r);
            float4 f4 = *reinterpret_cast<const float4*>(
                F + ((size_t)b * NNq + kc + r) * FDq + col);
            f4.x *= vsc; f4.y *= vsc; f4.z *= vsc; f4.w *= vsc;
            *reinterpret_cast<float4*>(Bs + r * 260 + col) = f4;
        }
        __syncthreads();
#pragma unroll 2
        for (int k = 0; k < 32; k++) {
            unsigned long long a2[4];
#pragma unroll
            for (int i = 0; i < 4; i++) {
                float a = As[(ty * 4 + i) * 33 + k];
                a2[i] = pack2(a, a);
            }
#pragma unroll
            for (int jj = 0; jj < 4; jj++) {
                const unsigned long long* bp =
                    reinterpret_cast<const unsigned long long*>(Bs + k * 260 + tx * 4 + 64 * jj);
                unsigned long long b0 = bp[0], b1 = bp[1];
#pragma unroll
                for (int i = 0; i < 4; i++) {
                    fma2(acc2[i][jj * 2 + 0], a2[i], b0);
                    fma2(acc2[i][jj * 2 + 1], a2[i], b1);
                }
            }
        }
        __syncthreads();
    }
#pragma unroll
    for (int i = 0; i < 4; i++) {
        int row = it * 64 + ty * 4 + i;
        float ui = __ldg(ub + row);
#pragma unroll
        for (int jj = 0; jj < 4; jj++) {
            float2 p0 = unpack2(acc2[i][jj * 2 + 0]);
            float2 p1 = unpack2(acc2[i][jj * 2 + 1]);
            float4 o;
            o.x = ui * p0.x; o.y = ui * p0.y;
            o.z = ui * p1.x; o.w = ui * p1.y;
            *reinterpret_cast<float4*>(
                outFt + ((size_t)b * NNq + row) * FDq + tx * 4 + 64 * jj) = o;
        }
    }
}

// ============================================================
extern "C" void kernel_launch(void* const* d_in, const int* in_sizes, int n_in,
                              void* d_out, int out_size)
{
    const float* S      = (const float*)d_in[0];
    const float* F      = (const float*)d_in[1];
    const float* W_s    = (const float*)d_in[2];
    const float* b_s    = (const float*)d_in[3];
    const float* g_s    = (const float*)d_in[4];
    const float* beta_s = (const float*)d_in[5];
    const float* W_f    = (const float*)d_in[6];
    const float* b_f    = (const float*)d_in[7];
    const float* g_f    = (const float*)d_in[8];
    const float* beta_f = (const float*)d_in[9];

    float* outP  = (float*)d_out;                               // [B,N,N]
    float* outFt = (float*)d_out + (size_t)BN * NNq * NNq;      // [B,N,FD]

    proj_kernel<<<(BN * NNq) / 64, 256>>>(S, W_s, b_s, g_s, beta_s, 0);
    proj_kernel<<<(BN * NNq) / 64, 256>>>(F, W_f, b_f, g_f, beta_f, 1);

    dim3 gcos(NNq / 64, NNq / 64, BN);
    cosk_kernel<<<gcos, 256>>>();

    sinkhorn_kernel<<<BN, 512>>>();

    dim3 gft(NNq / 64, BN);
    ftilde_kernel<<<gft, 256>>>(F, outP, outFt);
}

// round 11
// speedup vs baseline: 1.9996x; 1.0820x over previous
#include <cuda_runtime.h>
#include <cuda_bf16.h>

#define BN 128
#define NNq 512
#define PDq 128
#define SDq 256
#define FDq 256
#define NITERS 30

__device__ float g_Sp[BN * NNq * PDq];
__device__ float g_Fp[BN * NNq * PDq];
__device__ float g_K[(size_t)BN * NNq * NNq];
__device__ __nv_bfloat16 g_Kh[(size_t)BN * NNq * NNq];
__device__ float g_u[BN * NNq];
__device__ float g_v[BN * NNq];

__device__ __forceinline__ unsigned long long pack2(float x, float y) {
    unsigned long long r;
    asm("mov.b64 %0, {%1, %2};" : "=l"(r) : "f"(x), "f"(y));
    return r;
}
__device__ __forceinline__ void fma2(unsigned long long& d,
                                     unsigned long long a, unsigned long long b) {
    asm("fma.rn.f32x2 %0, %1, %2, %0;" : "+l"(d) : "l"(a), "l"(b));
}
__device__ __forceinline__ float2 unpack2(unsigned long long v) {
    float lo, hi;
    asm("mov.b64 {%0, %1}, %2;" : "=f"(lo), "=f"(hi) : "l"(v));
    return make_float2(lo, hi);
}

// ============================================================
// K1: H = X@W + b ; LayerNorm ; L2norm -> g_Sp/g_Fp
// ============================================================
__global__ __launch_bounds__(256) void proj_kernel(
    const float* __restrict__ X, const float* __restrict__ W,
    const float* __restrict__ bias, const float* __restrict__ gamma,
    const float* __restrict__ beta, int which)
{
    __shared__ float buf[8192];
    float* Xs = buf;                 // [64][33]
    float* Ws = buf + 64 * 33;       // [32][128]
    float* outp = which ? g_Fp : g_Sp;
    int t = threadIdx.x, tx = t & 15, ty = t >> 4;
    int row0 = blockIdx.x * 64;

    unsigned long long acc2[4][4];
#pragma unroll
    for (int i = 0; i < 4; i++)
#pragma unroll
        for (int j = 0; j < 4; j++) acc2[i][j] = 0ull;

    for (int kc = 0; kc < SDq; kc += 32) {
#pragma unroll
        for (int l = 0; l < 2; l++) {
            int r = (t >> 3) + 32 * l, c4 = (t & 7) * 4;
            float4 v = *reinterpret_cast<const float4*>(X + (size_t)(row0 + r) * SDq + kc + c4);
            Xs[r * 33 + c4] = v.x; Xs[r * 33 + c4 + 1] = v.y;
            Xs[r * 33 + c4 + 2] = v.z; Xs[r * 33 + c4 + 3] = v.w;
        }
#pragma unroll
        for (int l = 0; l < 4; l++) {
            int r = (t >> 5) + 8 * l, c4 = (t & 31) * 4;
            *reinterpret_cast<float4*>(Ws + r * 128 + c4) =
                *reinterpret_cast<const float4*>(W + (size_t)(kc + r) * PDq + c4);
        }
        __syncthreads();
#pragma unroll
        for (int k = 0; k < 32; k++) {
            unsigned long long a2[4], w2[4];
#pragma unroll
            for (int i = 0; i < 4; i++) {
                float a = Xs[(ty * 4 + i) * 33 + k];
                a2[i] = pack2(a, a);
            }
#pragma unroll
            for (int j = 0; j < 4; j++)
                w2[j] = *reinterpret_cast<const unsigned long long*>(Ws + k * 128 + tx * 8 + 2 * j);
#pragma unroll
            for (int i = 0; i < 4; i++)
#pragma unroll
                for (int j = 0; j < 4; j++) fma2(acc2[i][j], a2[i], w2[j]);
        }
        __syncthreads();
    }

    float* Hs = buf;  // reuse as [64][128]
#pragma unroll
    for (int i = 0; i < 4; i++) {
        int r = ty * 4 + i;
#pragma unroll
        for (int j = 0; j < 4; j++) {
            float2 p = unpack2(acc2[i][j]);
            int c = tx * 8 + 2 * j;
            Hs[r * 128 + c] = p.x + __ldg(bias + c);
            Hs[r * 128 + c + 1] = p.y + __ldg(bias + c + 1);
        }
    }
    __syncthreads();

    int w = t >> 5, lane = t & 31;
    for (int q = 0; q < 8; q++) {
        int r = w * 8 + q;
        float h[4];
#pragma unroll
        for (int j = 0; j < 4; j++) h[j] = Hs[r * 128 + lane + 32 * j];
        float s = h[0] + h[1] + h[2] + h[3];
#pragma unroll
        for (int o = 16; o; o >>= 1) s += __shfl_xor_sync(0xffffffffu, s, o);
        float mu = s * (1.0f / 128.0f);
        float vsm = 0.f;
#pragma unroll
        for (int j = 0; j < 4; j++) { float d = h[j] - mu; vsm += d * d; }
#pragma unroll
        for (int o = 16; o; o >>= 1) vsm += __shfl_xor_sync(0xffffffffu, vsm, o);
        float rstd = rsqrtf(vsm * (1.0f / 128.0f) + 1e-5f);
        float y[4]; float ss = 0.f;
#pragma unroll
        for (int j = 0; j < 4; j++) {
            int c = lane + 32 * j;
            y[j] = (h[j] - mu) * rstd * __ldg(gamma + c) + __ldg(beta + c);
            ss += y[j] * y[j];
        }
#pragma unroll
        for (int o = 16; o; o >>= 1) ss += __shfl_xor_sync(0xffffffffu, ss, o);
        float inv = 1.0f / fmaxf(sqrtf(ss), 1e-12f);
        size_t ob = (size_t)(row0 + r) * PDq;
#pragma unroll
        for (int j = 0; j < 4; j++) outp[ob + lane + 32 * j] = y[j] * inv;
    }
}

// ============================================================
// K2: cos = Sp@Fp^T ; K = exp(-10*clip(1-cos,0,2)) -> g_K + g_Kh
// B tile stored k-major (transposed) so d-pairs are contiguous -> f32x2 FMA.
// Accumulation order per element identical to scalar version.
// ============================================================
__global__ __launch_bounds__(256) void cosk_kernel()
{
    __shared__ float As[64 * 65];    // [row][k]
    __shared__ float Bs[64 * 66];    // [k][col] transposed, pitch 66 (8B-aligned pairs)
    int t = threadIdx.x, tx = t & 15, ty = t >> 4;
    int jt = blockIdx.x, it = blockIdx.y, b = blockIdx.z;
    const float* Ab = g_Sp + ((size_t)b * NNq + it * 64) * PDq;
    const float* Bb = g_Fp + ((size_t)b * NNq + jt * 64) * PDq;

    unsigned long long acc2[4][2];
#pragma unroll
    for (int i = 0; i < 4; i++) { acc2[i][0] = 0ull; acc2[i][1] = 0ull; }

    for (int kc = 0; kc < PDq; kc += 64) {
#pragma unroll
        for (int l = 0; l < 4; l++) {
            int r = (t >> 4) + 16 * l, c4 = (t & 15) * 4;
            float4 va = *reinterpret_cast<const float4*>(Ab + (size_t)r * PDq + kc + c4);
            As[r * 65 + c4] = va.x; As[r * 65 + c4 + 1] = va.y;
            As[r * 65 + c4 + 2] = va.z; As[r * 65 + c4 + 3] = va.w;
            float4 vb = *reinterpret_cast<const float4*>(Bb + (size_t)r * PDq + kc + c4);
            Bs[(c4 + 0) * 66 + r] = vb.x;
            Bs[(c4 + 1) * 66 + r] = vb.y;
            Bs[(c4 + 2) * 66 + r] = vb.z;
            Bs[(c4 + 3) * 66 + r] = vb.w;
        }
        __syncthreads();
#pragma unroll 8
        for (int k = 0; k < 64; k++) {
            unsigned long long b0 =
                *reinterpret_cast<const unsigned long long*>(Bs + k * 66 + tx * 4);
            unsigned long long b1 =
                *reinterpret_cast<const unsigned long long*>(Bs + k * 66 + tx * 4 + 2);
#pragma unroll
            for (int i = 0; i < 4; i++) {
                float a = As[(ty * 4 + i) * 65 + k];
                unsigned long long a2 = pack2(a, a);
                fma2(acc2[i][0], a2, b0);
                fma2(acc2[i][1], a2, b1);
            }
        }
        __syncthreads();
    }
#pragma unroll
    for (int i = 0; i < 4; i++) {
        float2 p0 = unpack2(acc2[i][0]);
        float2 p1 = unpack2(acc2[i][1]);
        float4 o;
        o.x = __expf(-10.0f * fminf(fmaxf(1.0f - p0.x, 0.f), 2.f));
        o.y = __expf(-10.0f * fminf(fmaxf(1.0f - p0.y, 0.f), 2.f));
        o.z = __expf(-10.0f * fminf(fmaxf(1.0f - p1.x, 0.f), 2.f));
        o.w = __expf(-10.0f * fminf(fmaxf(1.0f - p1.y, 0.f), 2.f));
        size_t idx = ((size_t)b * NNq + it * 64 + ty * 4 + i) * NNq + jt * 64 + tx * 4;
        *reinterpret_cast<float4*>(g_K + idx) = o;
        __nv_bfloat162 h0 = __floats2bfloat162_rn(o.x, o.y);
        __nv_bfloat162 h1 = __floats2bfloat162_rn(o.z, o.w);
        uint2 hh;
        hh.x = *reinterpret_cast<unsigned int*>(&h0);
        hh.y = *reinterpret_cast<unsigned int*>(&h1);
        *reinterpret_cast<uint2*>(g_Kh + idx) = hh;
    }
}

// ============================================================
// K3: Sinkhorn 30 iters on bf16 K (L2-resident).
// 1 CTA/batch, 1024 thr (32 warps, 16 rows each) for occupancy/latency hiding.
// Lane l owns 16 cols: {8l..8l+7, 256+8l..256+8l+7}.
// Two-stage cross-warp partial reduction keeps smem at 36KB (static).
// ============================================================
__global__ __launch_bounds__(1024) void sinkhorn_kernel()
{
    __shared__ float vs[512];
    __shared__ float us[512];
    __shared__ float part[16 * 512];
    int t = threadIdx.x, w = t >> 5, l = t & 31, b = blockIdx.x;
    const uint4* Kb = reinterpret_cast<const uint4*>(g_Kh + (size_t)b * NNq * NNq);

    if (t < 512) vs[t] = 1.0f;
    __syncthreads();
    const float rr = 1.0f / 512.0f;

    for (int iter = 0; iter < NITERS; ++iter) {
        float acc[16];
#pragma unroll
        for (int i = 0; i < 16; i++) acc[i] = 0.f;

        // preload v for this lane's 16 owned columns
        float va[16];
#pragma unroll
        for (int h = 0; h < 2; h++) {
            float4 v0 = *reinterpret_cast<const float4*>(vs + 256 * h + 8 * l);
            float4 v1 = *reinterpret_cast<const float4*>(vs + 256 * h + 8 * l + 4);
            va[h * 8 + 0] = v0.x; va[h * 8 + 1] = v0.y;
            va[h * 8 + 2] = v0.z; va[h * 8 + 3] = v0.w;
            va[h * 8 + 4] = v1.x; va[h * 8 + 5] = v1.y;
            va[h * 8 + 6] = v1.z; va[h * 8 + 7] = v1.w;
        }

#pragma unroll 1
        for (int row = w * 16; row < w * 16 + 16; ++row) {
            uint4 k0 = Kb[(size_t)row * 64 + l];
            uint4 k1 = Kb[(size_t)row * 64 + 32 + l];
            float kf[16];
            kf[0]  = __uint_as_float(k0.x << 16);
            kf[1]  = __uint_as_float(k0.x & 0xffff0000u);
            kf[2]  = __uint_as_float(k0.y << 16);
            kf[3]  = __uint_as_float(k0.y & 0xffff0000u);
            kf[4]  = __uint_as_float(k0.z << 16);
            kf[5]  = __uint_as_float(k0.z & 0xffff0000u);
            kf[6]  = __uint_as_float(k0.w << 16);
            kf[7]  = __uint_as_float(k0.w & 0xffff0000u);
            kf[8]  = __uint_as_float(k1.x << 16);
            kf[9]  = __uint_as_float(k1.x & 0xffff0000u);
            kf[10] = __uint_as_float(k1.y << 16);
            kf[11] = __uint_as_float(k1.y & 0xffff0000u);
            kf[12] = __uint_as_float(k1.z << 16);
            kf[13] = __uint_as_float(k1.z & 0xffff0000u);
            kf[14] = __uint_as_float(k1.w << 16);
            kf[15] = __uint_as_float(k1.w & 0xffff0000u);

            float s = 0.f;
#pragma unroll
            for (int i = 0; i < 16; i++) s += kf[i] * va[i];
#pragma unroll
            for (int o = 16; o; o >>= 1) s += __shfl_xor_sync(0xffffffffu, s, o);
            float u = rr / (s + 1e-8f);          // unclipped u feeds K^T u (matches ref)
            if (l == 0) us[row] = u;
#pragma unroll
            for (int i = 0; i < 16; i++) acc[i] += u * kf[i];
        }

        // stage 1: high warps (16..31) publish partials
        if (w >= 16) {
            int wb = (w - 16) * 512;
#pragma unroll
            for (int h = 0; h < 2; h++) {
                *reinterpret_cast<float4*>(part + wb + 256 * h + 8 * l) =
                    make_float4(acc[h * 8 + 0], acc[h * 8 + 1], acc[h * 8 + 2], acc[h * 8 + 3]);
                *reinterpret_cast<float4*>(part + wb + 256 * h + 8 * l + 4) =
                    make_float4(acc[h * 8 + 4], acc[h * 8 + 5], acc[h * 8 + 6], acc[h * 8 + 7]);
            }
        }
        __syncthreads();
        // stage 2: low warps (0..15) merge their partials in
        if (w < 16) {
            int wb = w * 512;
#pragma unroll
            for (int h = 0; h < 2; h++) {
                float4 p0 = *reinterpret_cast<const float4*>(part + wb + 256 * h + 8 * l);
                float4 p1 = *reinterpret_cast<const float4*>(part + wb + 256 * h + 8 * l + 4);
                p0.x += acc[h * 8 + 0]; p0.y += acc[h * 8 + 1];
                p0.z += acc[h * 8 + 2]; p0.w += acc[h * 8 + 3];
                p1.x += acc[h * 8 + 4]; p1.y += acc[h * 8 + 5];
                p1.z += acc[h * 8 + 6]; p1.w += acc[h * 8 + 7];
                *reinterpret_cast<float4*>(part + wb + 256 * h + 8 * l) = p0;
                *reinterpret_cast<float4*>(part + wb + 256 * h + 8 * l + 4) = p1;
            }
        }
        __syncthreads();

        if (t < 512) {
            float kt = 0.f;
#pragma unroll
            for (int ww = 0; ww < 16; ++ww) kt += part[ww * 512 + t];
            float v = rr / (kt + 1e-8f);
            vs[t] = fminf(fmaxf(v, 1e-8f), 1e8f);   // clipped v for next iter (matches ref)
        }
        __syncthreads();
    }
    if (t < 512) {
        g_u[b * NNq + t] = fminf(fmaxf(us[t], 1e-8f), 1e8f);
        g_v[b * NNq + t] = vs[t];
    }
}

// ============================================================
// K4: P = u*K*v (fused into K load) ; Ft = u * (K @ (v*F))
// grid (8 row-tiles, 128 batches), 256 thr. Packed f32x2 inner loop.
// ============================================================
__global__ __launch_bounds__(256) void ftilde_kernel(
    const float* __restrict__ F, float* __restrict__ outP, float* __restrict__ outFt)
{
    __shared__ float As[64 * 33];    // K tile [row][k]
    __shared__ float Bs[32 * 260];   // G tile [k][d], G = v (*) F
    int t = threadIdx.x, tx = t & 15, ty = t >> 4;
    int it = blockIdx.x, b = blockIdx.y;
    const float* ub = g_u + b * NNq;
    const float* vb = g_v + b * NNq;

    unsigned long long acc2[4][8];
#pragma unroll
    for (int i = 0; i < 4; i++)
#pragma unroll
        for (int j = 0; j < 8; j++) acc2[i][j] = 0ull;

    for (int kc = 0; kc < NNq; kc += 32) {
#pragma unroll
        for (int l = 0; l < 2; l++) {
            int r = t >> 2, col = (t & 3) * 4 + 16 * l;
            size_t gidx = ((size_t)b * NNq + it * 64 + r) * NNq + kc + col;
            float4 kv = *reinterpret_cast<const float4*>(g_K + gidx);
            As[r * 33 + col] = kv.x; As[r * 33 + col + 1] = kv.y;
            As[r * 33 + col + 2] = kv.z; As[r * 33 + col + 3] = kv.w;
            float ui = __ldg(ub + it * 64 + r);
            float4 v4 = *reinterpret_cast<const float4*>(vb + kc + col);
            float4 p;
            p.x = kv.x * ui * v4.x; p.y = kv.y * ui * v4.y;
            p.z = kv.z * ui * v4.z; p.w = kv.w * ui * v4.w;
            *reinterpret_cast<float4*>(outP + gidx) = p;
        }
#pragma unroll
        for (int jj = 0; jj < 8; jj++) {
            int r = t >> 3, col = (t & 7) * 4 + 32 * jj;
            float vsc = __ldg(vb + kc + r);
            float4 f4 = *reinterpret_cast<const float4*>(
                F + ((size_t)b * NNq + kc + r) * FDq + col);
            f4.x *= vsc; f4.y *= vsc; f4.z *= vsc; f4.w *= vsc;
            *reinterpret_cast<float4*>(Bs + r * 260 + col) = f4;
        }
        __syncthreads();
#pragma unroll 2
        for (int k = 0; k < 32; k++) {
            unsigned long long a2[4];
#pragma unroll
            for (int i = 0; i < 4; i++) {
                float a = As[(ty * 4 + i) * 33 + k];
                a2[i] = pack2(a, a);
            }
#pragma unroll
            for (int jj = 0; jj < 4; jj++) {
                const unsigned long long* bp =
                    reinterpret_cast<const unsigned long long*>(Bs + k * 260 + tx * 4 + 64 * jj);
                unsigned long long b0 = bp[0], b1 = bp[1];
#pragma unroll
                for (int i = 0; i < 4; i++) {
                    fma2(acc2[i][jj * 2 + 0], a2[i], b0);
                    fma2(acc2[i][jj * 2 + 1], a2[i], b1);
                }
            }
        }
        __syncthreads();
    }
#pragma unroll
    for (int i = 0; i < 4; i++) {
        int row = it * 64 + ty * 4 + i;
        float ui = __ldg(ub + row);
#pragma unroll
        for (int jj = 0; jj < 4; jj++) {
            float2 p0 = unpack2(acc2[i][jj * 2 + 0]);
            float2 p1 = unpack2(acc2[i][jj * 2 + 1]);
            float4 o;
            o.x = ui * p0.x; o.y = ui * p0.y;
            o.z = ui * p1.x; o.w = ui * p1.y;
            *reinterpret_cast<float4*>(
                outFt + ((size_t)b * NNq + row) * FDq + tx * 4 + 64 * jj) = o;
        }
    }
}

// ============================================================
extern "C" void kernel_launch(void* const* d_in, const int* in_sizes, int n_in,
                              void* d_out, int out_size)
{
    const float* S      = (const float*)d_in[0];
    const float* F      = (const float*)d_in[1];
    const float* W_s    = (const float*)d_in[2];
    const float* b_s    = (const float*)d_in[3];
    const float* g_s    = (const float*)d_in[4];
    const float* beta_s = (const float*)d_in[5];
    const float* W_f    = (const float*)d_in[6];
    const float* b_f    = (const float*)d_in[7];
    const float* g_f    = (const float*)d_in[8];
    const float* beta_f = (const float*)d_in[9];

    float* outP  = (float*)d_out;                               // [B,N,N]
    float* outFt = (float*)d_out + (size_t)BN * NNq * NNq;      // [B,N,FD]

    proj_kernel<<<(BN * NNq) / 64, 256>>>(S, W_s, b_s, g_s, beta_s, 0);
    proj_kernel<<<(BN * NNq) / 64, 256>>>(F, W_f, b_f, g_f, beta_f, 1);

    dim3 gcos(NNq / 64, NNq / 64, BN);
    cosk_kernel<<<gcos, 256>>>();

    sinkhorn_kernel<<<BN, 1024>>>();

    dim3 gft(NNq / 64, BN);
    ftilde_kernel<<<gft, 256>>>(F, outP, outFt);
}

// round 14
// speedup vs baseline: 2.3398x; 1.1702x over previous
#include <cuda_runtime.h>
#include <cuda_bf16.h>

#define BN 128
#define NNq 512
#define PDq 128
#define SDq 256
#define FDq 256
#define NITERS 30

typedef unsigned long long ull;

__device__ float g_Sp[BN * NNq * PDq];
__device__ float g_Fp[BN * NNq * PDq];
__device__ float g_K[(size_t)BN * NNq * NNq];
__device__ __nv_bfloat16 g_Kh[(size_t)BN * NNq * NNq];
__device__ float g_u[BN * NNq];
__device__ float g_v[BN * NNq];

__device__ __forceinline__ ull pack2(float x, float y) {
    ull r;
    asm("mov.b64 %0, {%1, %2};" : "=l"(r) : "f"(x), "f"(y));
    return r;
}
__device__ __forceinline__ void fma2(ull& d, ull a, ull b) {
    asm("fma.rn.f32x2 %0, %1, %2, %0;" : "+l"(d) : "l"(a), "l"(b));
}
__device__ __forceinline__ float2 unpack2(ull v) {
    float lo, hi;
    asm("mov.b64 {%0, %1}, %2;" : "=f"(lo), "=f"(hi) : "l"(v));
    return make_float2(lo, hi);
}

// ============================================================
// K1: H = X@W + b ; LayerNorm ; L2norm -> g_Sp/g_Fp
// 64x128 tile, 256 thr. A stored as dup (a,a) pairs -> no pack.
// W cols per thread: {tx*2, tx*2+1} + 32h  (conflict-free LDS.64).
// ============================================================
__global__ __launch_bounds__(256) void proj_kernel(
    const float* __restrict__ X, const float* __restrict__ W,
    const float* __restrict__ bias, const float* __restrict__ gamma,
    const float* __restrict__ beta, int which)
{
    __shared__ __align__(16) char sraw[33280];
    ull*   Xs2 = reinterpret_cast<ull*>(sraw);            // [64][33] dup pairs
    float* Ws  = reinterpret_cast<float*>(sraw + 16896);  // [32][128]
    float* outp = which ? g_Fp : g_Sp;
    int t = threadIdx.x, tx = t & 15, ty = t >> 4;
    int row0 = blockIdx.x * 64;

    ull acc2[4][4];
#pragma unroll
    for (int i = 0; i < 4; i++)
#pragma unroll
        for (int j = 0; j < 4; j++) acc2[i][j] = 0ull;

    for (int kc = 0; kc < SDq; kc += 32) {
#pragma unroll
        for (int l = 0; l < 2; l++) {
            int r = t >> 2, c4 = (t & 3) * 4 + 16 * l;
            float4 v = *reinterpret_cast<const float4*>(X + (size_t)(row0 + r) * SDq + kc + c4);
            Xs2[r * 33 + c4 + 0] = pack2(v.x, v.x);
            Xs2[r * 33 + c4 + 1] = pack2(v.y, v.y);
            Xs2[r * 33 + c4 + 2] = pack2(v.z, v.z);
            Xs2[r * 33 + c4 + 3] = pack2(v.w, v.w);
        }
#pragma unroll
        for (int l = 0; l < 4; l++) {
            int r = (t >> 5) + 8 * l, c4 = (t & 31) * 4;
            *reinterpret_cast<float4*>(Ws + r * 128 + c4) =
                *reinterpret_cast<const float4*>(W + (size_t)(kc + r) * PDq + c4);
        }
        __syncthreads();
#pragma unroll
        for (int k = 0; k < 32; k++) {
            ull a2[4], w2[4];
#pragma unroll
            for (int i = 0; i < 4; i++) a2[i] = Xs2[(ty * 4 + i) * 33 + k];
#pragma unroll
            for (int h = 0; h < 4; h++)
                w2[h] = *reinterpret_cast<const ull*>(Ws + k * 128 + tx * 2 + 32 * h);
#pragma unroll
            for (int i = 0; i < 4; i++)
#pragma unroll
                for (int h = 0; h < 4; h++) fma2(acc2[i][h], a2[i], w2[h]);
        }
        __syncthreads();
    }

    float* Hs = reinterpret_cast<float*>(sraw);  // [64][128]
#pragma unroll
    for (int i = 0; i < 4; i++) {
        int r = ty * 4 + i;
#pragma unroll
        for (int h = 0; h < 4; h++) {
            float2 p = unpack2(acc2[i][h]);
            int c = tx * 2 + 32 * h;
            Hs[r * 128 + c]     = p.x + __ldg(bias + c);
            Hs[r * 128 + c + 1] = p.y + __ldg(bias + c + 1);
        }
    }
    __syncthreads();

    int w = t >> 5, lane = t & 31;
    for (int q = 0; q < 8; q++) {
        int r = w * 8 + q;
        float h[4];
#pragma unroll
        for (int j = 0; j < 4; j++) h[j] = Hs[r * 128 + lane + 32 * j];
        float s = h[0] + h[1] + h[2] + h[3];
#pragma unroll
        for (int o = 16; o; o >>= 1) s += __shfl_xor_sync(0xffffffffu, s, o);
        float mu = s * (1.0f / 128.0f);
        float vsm = 0.f;
#pragma unroll
        for (int j = 0; j < 4; j++) { float d = h[j] - mu; vsm += d * d; }
#pragma unroll
        for (int o = 16; o; o >>= 1) vsm += __shfl_xor_sync(0xffffffffu, vsm, o);
        float rstd = rsqrtf(vsm * (1.0f / 128.0f) + 1e-5f);
        float y[4]; float ss = 0.f;
#pragma unroll
        for (int j = 0; j < 4; j++) {
            int c = lane + 32 * j;
            y[j] = (h[j] - mu) * rstd * __ldg(gamma + c) + __ldg(beta + c);
            ss += y[j] * y[j];
        }
#pragma unroll
        for (int o = 16; o; o >>= 1) ss += __shfl_xor_sync(0xffffffffu, ss, o);
        float inv = 1.0f / fmaxf(sqrtf(ss), 1e-12f);
        size_t ob = (size_t)(row0 + r) * PDq;
#pragma unroll
        for (int j = 0; j < 4; j++) outp[ob + lane + 32 * j] = y[j] * inv;
    }
}

// ============================================================
// K2: cos = Sp@Fp^T ; K = exp(-10*clip(1-cos,0,2)) -> g_K + g_Kh
// 128x128 tile, 256 thr, 8x8 per thread. Dup-pair A (no pack),
// B k-major. Cols per thread: {tx*2, tx*2+1} + 32h (conflict-free).
// k-chunks of 16. 73% FFMA2 issue density.
// ============================================================
__global__ __launch_bounds__(256) void cosk_kernel()
{
    __shared__ ull As2[128 * 17];     // dup pairs [row][k]
    __shared__ float Bs[16 * 130];    // [k][col]
    int t = threadIdx.x, tx = t & 15, ty = t >> 4;
    int jt = blockIdx.x, it = blockIdx.y, b = blockIdx.z;
    const float* Ab = g_Sp + ((size_t)b * NNq + it * 128) * PDq;
    const float* Bb = g_Fp + ((size_t)b * NNq + jt * 128) * PDq;

    ull acc2[8][4];
#pragma unroll
    for (int i = 0; i < 8; i++)
#pragma unroll
        for (int h = 0; h < 4; h++) acc2[i][h] = 0ull;

    for (int kc = 0; kc < PDq; kc += 16) {
#pragma unroll
        for (int l = 0; l < 2; l++) {
            int r = (t >> 2) + 64 * l, c4 = (t & 3) * 4;
            float4 va = *reinterpret_cast<const float4*>(Ab + (size_t)r * PDq + kc + c4);
            As2[r * 17 + c4 + 0] = pack2(va.x, va.x);
            As2[r * 17 + c4 + 1] = pack2(va.y, va.y);
            As2[r * 17 + c4 + 2] = pack2(va.z, va.z);
            As2[r * 17 + c4 + 3] = pack2(va.w, va.w);
            float4 vb = *reinterpret_cast<const float4*>(Bb + (size_t)r * PDq + kc + c4);
            Bs[(c4 + 0) * 130 + r] = vb.x;
            Bs[(c4 + 1) * 130 + r] = vb.y;
            Bs[(c4 + 2) * 130 + r] = vb.z;
            Bs[(c4 + 3) * 130 + r] = vb.w;
        }
        __syncthreads();
#pragma unroll
        for (int k = 0; k < 16; k++) {
            ull b2[4];
#pragma unroll
            for (int h = 0; h < 4; h++)
                b2[h] = *reinterpret_cast<const ull*>(Bs + k * 130 + tx * 2 + 32 * h);
#pragma unroll
            for (int i = 0; i < 8; i++) {
                ull a2 = As2[(ty * 8 + i) * 17 + k];
#pragma unroll
                for (int h = 0; h < 4; h++) fma2(acc2[i][h], a2, b2[h]);
            }
        }
        __syncthreads();
    }

#pragma unroll
    for (int i = 0; i < 8; i++) {
        int row = it * 128 + ty * 8 + i;
#pragma unroll
        for (int h = 0; h < 4; h++) {
            float2 p = unpack2(acc2[i][h]);
            float ex = __expf(-10.0f * fminf(fmaxf(1.0f - p.x, 0.f), 2.f));
            float ey = __expf(-10.0f * fminf(fmaxf(1.0f - p.y, 0.f), 2.f));
            size_t idx = ((size_t)b * NNq + row) * NNq + jt * 128 + tx * 2 + 32 * h;
            *reinterpret_cast<float2*>(g_K + idx) = make_float2(ex, ey);
            __nv_bfloat162 hh = __floats2bfloat162_rn(ex, ey);
            *reinterpret_cast<__nv_bfloat162*>(g_Kh + idx) = hh;
        }
    }
}

// ============================================================
// K3: Sinkhorn 30 iters on bf16 K (L2-resident). Unchanged from R10.
// ============================================================
__global__ __launch_bounds__(1024) void sinkhorn_kernel()
{
    __shared__ float vs[512];
    __shared__ float us[512];
    __shared__ float part[16 * 512];
    int t = threadIdx.x, w = t >> 5, l = t & 31, b = blockIdx.x;
    const uint4* Kb = reinterpret_cast<const uint4*>(g_Kh + (size_t)b * NNq * NNq);

    if (t < 512) vs[t] = 1.0f;
    __syncthreads();
    const float rr = 1.0f / 512.0f;

    for (int iter = 0; iter < NITERS; ++iter) {
        float acc[16];
#pragma unroll
        for (int i = 0; i < 16; i++) acc[i] = 0.f;

        float va[16];
#pragma unroll
        for (int h = 0; h < 2; h++) {
            float4 v0 = *reinterpret_cast<const float4*>(vs + 256 * h + 8 * l);
            float4 v1 = *reinterpret_cast<const float4*>(vs + 256 * h + 8 * l + 4);
            va[h * 8 + 0] = v0.x; va[h * 8 + 1] = v0.y;
            va[h * 8 + 2] = v0.z; va[h * 8 + 3] = v0.w;
            va[h * 8 + 4] = v1.x; va[h * 8 + 5] = v1.y;
            va[h * 8 + 6] = v1.z; va[h * 8 + 7] = v1.w;
        }

#pragma unroll 1
        for (int row = w * 16; row < w * 16 + 16; ++row) {
            uint4 k0 = Kb[(size_t)row * 64 + l];
            uint4 k1 = Kb[(size_t)row * 64 + 32 + l];
            float kf[16];
            kf[0]  = __uint_as_float(k0.x << 16);
            kf[1]  = __uint_as_float(k0.x & 0xffff0000u);
            kf[2]  = __uint_as_float(k0.y << 16);
            kf[3]  = __uint_as_float(k0.y & 0xffff0000u);
            kf[4]  = __uint_as_float(k0.z << 16);
            kf[5]  = __uint_as_float(k0.z & 0xffff0000u);
            kf[6]  = __uint_as_float(k0.w << 16);
            kf[7]  = __uint_as_float(k0.w & 0xffff0000u);
            kf[8]  = __uint_as_float(k1.x << 16);
            kf[9]  = __uint_as_float(k1.x & 0xffff0000u);
            kf[10] = __uint_as_float(k1.y << 16);
            kf[11] = __uint_as_float(k1.y & 0xffff0000u);
            kf[12] = __uint_as_float(k1.z << 16);
            kf[13] = __uint_as_float(k1.z & 0xffff0000u);
            kf[14] = __uint_as_float(k1.w << 16);
            kf[15] = __uint_as_float(k1.w & 0xffff0000u);

            float s = 0.f;
#pragma unroll
            for (int i = 0; i < 16; i++) s += kf[i] * va[i];
#pragma unroll
            for (int o = 16; o; o >>= 1) s += __shfl_xor_sync(0xffffffffu, s, o);
            float u = rr / (s + 1e-8f);
            if (l == 0) us[row] = u;
#pragma unroll
            for (int i = 0; i < 16; i++) acc[i] += u * kf[i];
        }

        if (w >= 16) {
            int wb = (w - 16) * 512;
#pragma unroll
            for (int h = 0; h < 2; h++) {
                *reinterpret_cast<float4*>(part + wb + 256 * h + 8 * l) =
                    make_float4(acc[h * 8 + 0], acc[h * 8 + 1], acc[h * 8 + 2], acc[h * 8 + 3]);
                *reinterpret_cast<float4*>(part + wb + 256 * h + 8 * l + 4) =
                    make_float4(acc[h * 8 + 4], acc[h * 8 + 5], acc[h * 8 + 6], acc[h * 8 + 7]);
            }
        }
        __syncthreads();
        if (w < 16) {
            int wb = w * 512;
#pragma unroll
            for (int h = 0; h < 2; h++) {
                float4 p0 = *reinterpret_cast<const float4*>(part + wb + 256 * h + 8 * l);
                float4 p1 = *reinterpret_cast<const float4*>(part + wb + 256 * h + 8 * l + 4);
                p0.x += acc[h * 8 + 0]; p0.y += acc[h * 8 + 1];
                p0.z += acc[h * 8 + 2]; p0.w += acc[h * 8 + 3];
                p1.x += acc[h * 8 + 4]; p1.y += acc[h * 8 + 5];
                p1.z += acc[h * 8 + 6]; p1.w += acc[h * 8 + 7];
                *reinterpret_cast<float4*>(part + wb + 256 * h + 8 * l) = p0;
                *reinterpret_cast<float4*>(part + wb + 256 * h + 8 * l + 4) = p1;
            }
        }
        __syncthreads();

        if (t < 512) {
            float kt = 0.f;
#pragma unroll
            for (int ww = 0; ww < 16; ++ww) kt += part[ww * 512 + t];
            float v = rr / (kt + 1e-8f);
            vs[t] = fminf(fmaxf(v, 1e-8f), 1e8f);
        }
        __syncthreads();
    }
    if (t < 512) {
        g_u[b * NNq + t] = fminf(fmaxf(us[t], 1e-8f), 1e8f);
        g_v[b * NNq + t] = vs[t];
    }
}

// ============================================================
// K4: P = u*K*v (fused into K load) ; Ft = u * (K @ (v*F))
// 64x256 tile, 256 thr, 4 rows x 16 d. Dup-pair A, conflict-free
// B cols {tx*2, tx*2+1} + 32jj. k-chunks of 16. 73% FFMA2 density.
// ============================================================
__global__ __launch_bounds__(256) void ftilde_kernel(
    const float* __restrict__ F, float* __restrict__ outP, float* __restrict__ outFt)
{
    __shared__ ull As2[64 * 17];      // K tile dup pairs [row][k]
    __shared__ float Bs[16 * 260];    // G tile [k][d], G = v (*) F
    int t = threadIdx.x, tx = t & 15, ty = t >> 4;
    int it = blockIdx.x, b = blockIdx.y;
    const float* ub = g_u + b * NNq;
    const float* vb = g_v + b * NNq;

    ull acc2[4][8];
#pragma unroll
    for (int i = 0; i < 4; i++)
#pragma unroll
        for (int j = 0; j < 8; j++) acc2[i][j] = 0ull;

    for (int kc = 0; kc < NNq; kc += 16) {
        // K tile (64x16) + fused P write; one float4 per thread
        {
            int r = t >> 2, col = (t & 3) * 4;
            size_t gidx = ((size_t)b * NNq + it * 64 + r) * NNq + kc + col;
            float4 kv = *reinterpret_cast<const float4*>(g_K + gidx);
            As2[r * 17 + col + 0] = pack2(kv.x, kv.x);
            As2[r * 17 + col + 1] = pack2(kv.y, kv.y);
            As2[r * 17 + col + 2] = pack2(kv.z, kv.z);
            As2[r * 17 + col + 3] = pack2(kv.w, kv.w);
            float ui = __ldg(ub + it * 64 + r);
            float4 v4 = *reinterpret_cast<const float4*>(vb + kc + col);
            float4 p;
            p.x = kv.x * ui * v4.x; p.y = kv.y * ui * v4.y;
            p.z = kv.z * ui * v4.z; p.w = kv.w * ui * v4.w;
            *reinterpret_cast<float4*>(outP + gidx) = p;
        }
        // G tile: 16 k-rows x 256 d; 4 float4 per thread
#pragma unroll
        for (int jj = 0; jj < 4; jj++) {
            int r = (t >> 6) + 4 * jj, col = (t & 63) * 4;
            float vsc = __ldg(vb + kc + r);
            float4 f4 = *reinterpret_cast<const float4*>(
                F + ((size_t)b * NNq + kc + r) * FDq + col);
            f4.x *= vsc; f4.y *= vsc; f4.z *= vsc; f4.w *= vsc;
            *reinterpret_cast<float4*>(Bs + r * 260 + col) = f4;
        }
        __syncthreads();
#pragma unroll
        for (int k = 0; k < 16; k++) {
            ull a2[4];
#pragma unroll
            for (int i = 0; i < 4; i++) a2[i] = As2[(ty * 4 + i) * 17 + k];
#pragma unroll
            for (int jj = 0; jj < 8; jj++) {
                ull b2 = *reinterpret_cast<const ull*>(Bs + k * 260 + tx * 2 + 32 * jj);
#pragma unroll
                for (int i = 0; i < 4; i++) fma2(acc2[i][jj], a2[i], b2);
            }
        }
        __syncthreads();
    }
#pragma unroll
    for (int i = 0; i < 4; i++) {
        int row = it * 64 + ty * 4 + i;
        float ui = __ldg(ub + row);
#pragma unroll
        for (int jj = 0; jj < 8; jj++) {
            float2 p = unpack2(acc2[i][jj]);
            p.x *= ui; p.y *= ui;
            *reinterpret_cast<float2*>(
                outFt + ((size_t)b * NNq + row) * FDq + tx * 2 + 32 * jj) = p;
        }
    }
}

// ============================================================
extern "C" void kernel_launch(void* const* d_in, const int* in_sizes, int n_in,
                              void* d_out, int out_size)
{
    const float* S      = (const float*)d_in[0];
    const float* F      = (const float*)d_in[1];
    const float* W_s    = (const float*)d_in[2];
    const float* b_s    = (const float*)d_in[3];
    const float* g_s    = (const float*)d_in[4];
    const float* beta_s = (const float*)d_in[5];
    const float* W_f    = (const float*)d_in[6];
    const float* b_f    = (const float*)d_in[7];
    const float* g_f    = (const float*)d_in[8];
    const float* beta_f = (const float*)d_in[9];

    float* outP  = (float*)d_out;                               // [B,N,N]
    float* outFt = (float*)d_out + (size_t)BN * NNq * NNq;      // [B,N,FD]

    proj_kernel<<<(BN * NNq) / 64, 256>>>(S, W_s, b_s, g_s, beta_s, 0);
    proj_kernel<<<(BN * NNq) / 64, 256>>>(F, W_f, b_f, g_f, beta_f, 1);

    dim3 gcos(NNq / 128, NNq / 128, BN);
    cosk_kernel<<<gcos, 256>>>();

    sinkhorn_kernel<<<BN, 1024>>>();

    dim3 gft(NNq / 64, BN);
    ftilde_kernel<<<gft, 256>>>(F, outP, outFt);
}

// round 15
// speedup vs baseline: 2.7649x; 1.1816x over previous
#include <cuda_runtime.h>
#include <cuda_bf16.h>

#define BN 128
#define NNq 512
#define PDq 128
#define SDq 256
#define FDq 256
#define NITERS 30

typedef unsigned long long ull;

__device__ float g_Sp[BN * NNq * PDq];
__device__ float g_Fp[BN * NNq * PDq];
__device__ __nv_bfloat16 g_Kh [(size_t)BN * NNq * NNq];   // K hi (bf16 rn)
__device__ __nv_bfloat16 g_Klo[(size_t)BN * NNq * NNq];   // K - float(Khi)
__device__ __nv_bfloat16 g_Ghi[(size_t)BN * NNq * FDq];   // (v*F) hi
__device__ __nv_bfloat16 g_Glo[(size_t)BN * NNq * FDq];   // (v*F) lo
__device__ float g_u[BN * NNq];
__device__ float g_v[BN * NNq];

__device__ __forceinline__ ull pack2(float x, float y) {
    ull r;
    asm("mov.b64 %0, {%1, %2};" : "=l"(r) : "f"(x), "f"(y));
    return r;
}
__device__ __forceinline__ void fma2(ull& d, ull a, ull b) {
    asm("fma.rn.f32x2 %0, %1, %2, %0;" : "+l"(d) : "l"(a), "l"(b));
}
__device__ __forceinline__ float2 unpack2(ull v) {
    float lo, hi;
    asm("mov.b64 {%0, %1}, %2;" : "=f"(lo), "=f"(hi) : "l"(v));
    return make_float2(lo, hi);
}
__device__ __forceinline__ unsigned smaddr(const void* p) {
    return (unsigned)__cvta_generic_to_shared(p);
}

#define LDSM_X4(r0, r1, r2, r3, a) \
    asm volatile("ldmatrix.sync.aligned.m8n8.x4.shared.b16 {%0,%1,%2,%3},[%4];" \
                 : "=r"(r0), "=r"(r1), "=r"(r2), "=r"(r3) : "r"(a))
#define LDSM_X4T(r0, r1, r2, r3, a) \
    asm volatile("ldmatrix.sync.aligned.m8n8.x4.trans.shared.b16 {%0,%1,%2,%3},[%4];" \
                 : "=r"(r0), "=r"(r1), "=r"(r2), "=r"(r3) : "r"(a))
#define MMA16816(c, a0, a1, a2, a3, b0, b1) \
    asm volatile("mma.sync.aligned.m16n8k16.row.col.f32.bf16.bf16.f32 " \
                 "{%0,%1,%2,%3},{%4,%5,%6,%7},{%8,%9},{%0,%1,%2,%3};" \
                 : "+f"((c)[0]), "+f"((c)[1]), "+f"((c)[2]), "+f"((c)[3]) \
                 : "r"(a0), "r"(a1), "r"(a2), "r"(a3), "r"(b0), "r"(b1))

// ============================================================
// K1: H = X@W + b ; LayerNorm ; L2norm -> g_Sp/g_Fp  (unchanged)
// ============================================================
__global__ __launch_bounds__(256) void proj_kernel(
    const float* __restrict__ X, const float* __restrict__ W,
    const float* __restrict__ bias, const float* __restrict__ gamma,
    const float* __restrict__ beta, int which)
{
    __shared__ __align__(16) char sraw[33280];
    ull*   Xs2 = reinterpret_cast<ull*>(sraw);            // [64][33] dup pairs
    float* Ws  = reinterpret_cast<float*>(sraw + 16896);  // [32][128]
    float* outp = which ? g_Fp : g_Sp;
    int t = threadIdx.x, tx = t & 15, ty = t >> 4;
    int row0 = blockIdx.x * 64;

    ull acc2[4][4];
#pragma unroll
    for (int i = 0; i < 4; i++)
#pragma unroll
        for (int j = 0; j < 4; j++) acc2[i][j] = 0ull;

    for (int kc = 0; kc < SDq; kc += 32) {
#pragma unroll
        for (int l = 0; l < 2; l++) {
            int r = t >> 2, c4 = (t & 3) * 4 + 16 * l;
            float4 v = *reinterpret_cast<const float4*>(X + (size_t)(row0 + r) * SDq + kc + c4);
            Xs2[r * 33 + c4 + 0] = pack2(v.x, v.x);
            Xs2[r * 33 + c4 + 1] = pack2(v.y, v.y);
            Xs2[r * 33 + c4 + 2] = pack2(v.z, v.z);
            Xs2[r * 33 + c4 + 3] = pack2(v.w, v.w);
        }
#pragma unroll
        for (int l = 0; l < 4; l++) {
            int r = (t >> 5) + 8 * l, c4 = (t & 31) * 4;
            *reinterpret_cast<float4*>(Ws + r * 128 + c4) =
                *reinterpret_cast<const float4*>(W + (size_t)(kc + r) * PDq + c4);
        }
        __syncthreads();
#pragma unroll
        for (int k = 0; k < 32; k++) {
            ull a2[4], w2[4];
#pragma unroll
            for (int i = 0; i < 4; i++) a2[i] = Xs2[(ty * 4 + i) * 33 + k];
#pragma unroll
            for (int h = 0; h < 4; h++)
                w2[h] = *reinterpret_cast<const ull*>(Ws + k * 128 + tx * 2 + 32 * h);
#pragma unroll
            for (int i = 0; i < 4; i++)
#pragma unroll
                for (int h = 0; h < 4; h++) fma2(acc2[i][h], a2[i], w2[h]);
        }
        __syncthreads();
    }

    float* Hs = reinterpret_cast<float*>(sraw);  // [64][128]
#pragma unroll
    for (int i = 0; i < 4; i++) {
        int r = ty * 4 + i;
#pragma unroll
        for (int h = 0; h < 4; h++) {
            float2 p = unpack2(acc2[i][h]);
            int c = tx * 2 + 32 * h;
            Hs[r * 128 + c]     = p.x + __ldg(bias + c);
            Hs[r * 128 + c + 1] = p.y + __ldg(bias + c + 1);
        }
    }
    __syncthreads();

    int w = t >> 5, lane = t & 31;
    for (int q = 0; q < 8; q++) {
        int r = w * 8 + q;
        float h[4];
#pragma unroll
        for (int j = 0; j < 4; j++) h[j] = Hs[r * 128 + lane + 32 * j];
        float s = h[0] + h[1] + h[2] + h[3];
#pragma unroll
        for (int o = 16; o; o >>= 1) s += __shfl_xor_sync(0xffffffffu, s, o);
        float mu = s * (1.0f / 128.0f);
        float vsm = 0.f;
#pragma unroll
        for (int j = 0; j < 4; j++) { float d = h[j] - mu; vsm += d * d; }
#pragma unroll
        for (int o = 16; o; o >>= 1) vsm += __shfl_xor_sync(0xffffffffu, vsm, o);
        float rstd = rsqrtf(vsm * (1.0f / 128.0f) + 1e-5f);
        float y[4]; float ss = 0.f;
#pragma unroll
        for (int j = 0; j < 4; j++) {
            int c = lane + 32 * j;
            y[j] = (h[j] - mu) * rstd * __ldg(gamma + c) + __ldg(beta + c);
            ss += y[j] * y[j];
        }
#pragma unroll
        for (int o = 16; o; o >>= 1) ss += __shfl_xor_sync(0xffffffffu, ss, o);
        float inv = 1.0f / fmaxf(sqrtf(ss), 1e-12f);
        size_t ob = (size_t)(row0 + r) * PDq;
#pragma unroll
        for (int j = 0; j < 4; j++) outp[ob + lane + 32 * j] = y[j] * inv;
    }
}

// ============================================================
// K2: cos = Sp@Fp^T ; K = exp(-10*clip(1-cos,0,2))
// NOW writes split bf16: g_Kh (hi, rn) + g_Klo (residual). No fp32 K.
// ============================================================
__global__ __launch_bounds__(256) void cosk_kernel()
{
    __shared__ ull As2[128 * 17];     // dup pairs [row][k]
    __shared__ float Bs[16 * 130];    // [k][col]
    int t = threadIdx.x, tx = t & 15, ty = t >> 4;
    int jt = blockIdx.x, it = blockIdx.y, b = blockIdx.z;
    const float* Ab = g_Sp + ((size_t)b * NNq + it * 128) * PDq;
    const float* Bb = g_Fp + ((size_t)b * NNq + jt * 128) * PDq;

    ull acc2[8][4];
#pragma unroll
    for (int i = 0; i < 8; i++)
#pragma unroll
        for (int h = 0; h < 4; h++) acc2[i][h] = 0ull;

    for (int kc = 0; kc < PDq; kc += 16) {
#pragma unroll
        for (int l = 0; l < 2; l++) {
            int r = (t >> 2) + 64 * l, c4 = (t & 3) * 4;
            float4 va = *reinterpret_cast<const float4*>(Ab + (size_t)r * PDq + kc + c4);
            As2[r * 17 + c4 + 0] = pack2(va.x, va.x);
            As2[r * 17 + c4 + 1] = pack2(va.y, va.y);
            As2[r * 17 + c4 + 2] = pack2(va.z, va.z);
            As2[r * 17 + c4 + 3] = pack2(va.w, va.w);
            float4 vb = *reinterpret_cast<const float4*>(Bb + (size_t)r * PDq + kc + c4);
            Bs[(c4 + 0) * 130 + r] = vb.x;
            Bs[(c4 + 1) * 130 + r] = vb.y;
            Bs[(c4 + 2) * 130 + r] = vb.z;
            Bs[(c4 + 3) * 130 + r] = vb.w;
        }
        __syncthreads();
#pragma unroll
        for (int k = 0; k < 16; k++) {
            ull b2[4];
#pragma unroll
            for (int h = 0; h < 4; h++)
                b2[h] = *reinterpret_cast<const ull*>(Bs + k * 130 + tx * 2 + 32 * h);
#pragma unroll
            for (int i = 0; i < 8; i++) {
                ull a2 = As2[(ty * 8 + i) * 17 + k];
#pragma unroll
                for (int h = 0; h < 4; h++) fma2(acc2[i][h], a2, b2[h]);
            }
        }
        __syncthreads();
    }

#pragma unroll
    for (int i = 0; i < 8; i++) {
        int row = it * 128 + ty * 8 + i;
#pragma unroll
        for (int h = 0; h < 4; h++) {
            float2 p = unpack2(acc2[i][h]);
            float ex = __expf(-10.0f * fminf(fmaxf(1.0f - p.x, 0.f), 2.f));
            float ey = __expf(-10.0f * fminf(fmaxf(1.0f - p.y, 0.f), 2.f));
            __nv_bfloat162 hi2 = __floats2bfloat162_rn(ex, ey);
            float hx = __bfloat162float(hi2.x);
            float hy = __bfloat162float(hi2.y);
            __nv_bfloat162 lo2 = __floats2bfloat162_rn(ex - hx, ey - hy);
            size_t idx = ((size_t)b * NNq + row) * NNq + jt * 128 + tx * 2 + 32 * h;
            *reinterpret_cast<__nv_bfloat162*>(g_Kh  + idx) = hi2;
            *reinterpret_cast<__nv_bfloat162*>(g_Klo + idx) = lo2;
        }
    }
}

// ============================================================
// K3: Sinkhorn 30 iters on bf16 Khi (L2-resident). Unchanged.
// ============================================================
__global__ __launch_bounds__(1024) void sinkhorn_kernel()
{
    __shared__ float vs[512];
    __shared__ float us[512];
    __shared__ float part[16 * 512];
    int t = threadIdx.x, w = t >> 5, l = t & 31, b = blockIdx.x;
    const uint4* Kb = reinterpret_cast<const uint4*>(g_Kh + (size_t)b * NNq * NNq);

    if (t < 512) vs[t] = 1.0f;
    __syncthreads();
    const float rr = 1.0f / 512.0f;

    for (int iter = 0; iter < NITERS; ++iter) {
        float acc[16];
#pragma unroll
        for (int i = 0; i < 16; i++) acc[i] = 0.f;

        float va[16];
#pragma unroll
        for (int h = 0; h < 2; h++) {
            float4 v0 = *reinterpret_cast<const float4*>(vs + 256 * h + 8 * l);
            float4 v1 = *reinterpret_cast<const float4*>(vs + 256 * h + 8 * l + 4);
            va[h * 8 + 0] = v0.x; va[h * 8 + 1] = v0.y;
            va[h * 8 + 2] = v0.z; va[h * 8 + 3] = v0.w;
            va[h * 8 + 4] = v1.x; va[h * 8 + 5] = v1.y;
            va[h * 8 + 6] = v1.z; va[h * 8 + 7] = v1.w;
        }

#pragma unroll 1
        for (int row = w * 16; row < w * 16 + 16; ++row) {
            uint4 k0 = Kb[(size_t)row * 64 + l];
            uint4 k1 = Kb[(size_t)row * 64 + 32 + l];
            float kf[16];
            kf[0]  = __uint_as_float(k0.x << 16);
            kf[1]  = __uint_as_float(k0.x & 0xffff0000u);
            kf[2]  = __uint_as_float(k0.y << 16);
            kf[3]  = __uint_as_float(k0.y & 0xffff0000u);
            kf[4]  = __uint_as_float(k0.z << 16);
            kf[5]  = __uint_as_float(k0.z & 0xffff0000u);
            kf[6]  = __uint_as_float(k0.w << 16);
            kf[7]  = __uint_as_float(k0.w & 0xffff0000u);
            kf[8]  = __uint_as_float(k1.x << 16);
            kf[9]  = __uint_as_float(k1.x & 0xffff0000u);
            kf[10] = __uint_as_float(k1.y << 16);
            kf[11] = __uint_as_float(k1.y & 0xffff0000u);
            kf[12] = __uint_as_float(k1.z << 16);
            kf[13] = __uint_as_float(k1.z & 0xffff0000u);
            kf[14] = __uint_as_float(k1.w << 16);
            kf[15] = __uint_as_float(k1.w & 0xffff0000u);

            float s = 0.f;
#pragma unroll
            for (int i = 0; i < 16; i++) s += kf[i] * va[i];
#pragma unroll
            for (int o = 16; o; o >>= 1) s += __shfl_xor_sync(0xffffffffu, s, o);
            float u = rr / (s + 1e-8f);
            if (l == 0) us[row] = u;
#pragma unroll
            for (int i = 0; i < 16; i++) acc[i] += u * kf[i];
        }

        if (w >= 16) {
            int wb = (w - 16) * 512;
#pragma unroll
            for (int h = 0; h < 2; h++) {
                *reinterpret_cast<float4*>(part + wb + 256 * h + 8 * l) =
                    make_float4(acc[h * 8 + 0], acc[h * 8 + 1], acc[h * 8 + 2], acc[h * 8 + 3]);
                *reinterpret_cast<float4*>(part + wb + 256 * h + 8 * l + 4) =
                    make_float4(acc[h * 8 + 4], acc[h * 8 + 5], acc[h * 8 + 6], acc[h * 8 + 7]);
            }
        }
        __syncthreads();
        if (w < 16) {
            int wb = w * 512;
#pragma unroll
            for (int h = 0; h < 2; h++) {
                float4 p0 = *reinterpret_cast<const float4*>(part + wb + 256 * h + 8 * l);
                float4 p1 = *reinterpret_cast<const float4*>(part + wb + 256 * h + 8 * l + 4);
                p0.x += acc[h * 8 + 0]; p0.y += acc[h * 8 + 1];
                p0.z += acc[h * 8 + 2]; p0.w += acc[h * 8 + 3];
                p1.x += acc[h * 8 + 4]; p1.y += acc[h * 8 + 5];
                p1.z += acc[h * 8 + 6]; p1.w += acc[h * 8 + 7];
                *reinterpret_cast<float4*>(part + wb + 256 * h + 8 * l) = p0;
                *reinterpret_cast<float4*>(part + wb + 256 * h + 8 * l + 4) = p1;
            }
        }
        __syncthreads();

        if (t < 512) {
            float kt = 0.f;
#pragma unroll
            for (int ww = 0; ww < 16; ++ww) kt += part[ww * 512 + t];
            float v = rr / (kt + 1e-8f);
            vs[t] = fminf(fmaxf(v, 1e-8f), 1e8f);
        }
        __syncthreads();
    }
    if (t < 512) {
        g_u[b * NNq + t] = fminf(fmaxf(us[t], 1e-8f), 1e8f);
        g_v[b * NNq + t] = vs[t];
    }
}

// ============================================================
// K3b: G = v (*) F  split into bf16 hi/lo  (g_Ghi, g_Glo)
// ============================================================
__global__ __launch_bounds__(256) void gprep_kernel(const float* __restrict__ F)
{
    int idx = blockIdx.x * 256 + threadIdx.x;        // one float4 per thread
    int b = idx >> 15;                               // 32768 quads per batch
    int rem = idx & 32767;
    int k = rem >> 6;
    int c4 = (rem & 63) * 4;
    float vsc = __ldg(g_v + b * NNq + k);
    size_t base = ((size_t)b * NNq + k) * FDq + c4;
    float4 f4 = *reinterpret_cast<const float4*>(F + base);
    float gx = f4.x * vsc, gy = f4.y * vsc, gz = f4.z * vsc, gw = f4.w * vsc;
    __nv_bfloat162 h0 = __floats2bfloat162_rn(gx, gy);
    __nv_bfloat162 h1 = __floats2bfloat162_rn(gz, gw);
    __nv_bfloat162 l0 = __floats2bfloat162_rn(gx - __bfloat162float(h0.x),
                                              gy - __bfloat162float(h0.y));
    __nv_bfloat162 l1 = __floats2bfloat162_rn(gz - __bfloat162float(h1.x),
                                              gw - __bfloat162float(h1.y));
    uint2 hh, ll;
    hh.x = *reinterpret_cast<unsigned*>(&h0); hh.y = *reinterpret_cast<unsigned*>(&h1);
    ll.x = *reinterpret_cast<unsigned*>(&l0); ll.y = *reinterpret_cast<unsigned*>(&l1);
    *reinterpret_cast<uint2*>(g_Ghi + base) = hh;
    *reinterpret_cast<uint2*>(g_Glo + base) = ll;
}

// ============================================================
// K4: tensor-core ftilde.  Ft = u * ((Khi+Klo) @ (Ghi+Glo)), bf16x3:
//     Khi@Ghi + Khi@Glo + Klo@Ghi  via mma.sync.m16n8k16 bf16.
//     P = u*(Khi+Klo)*v written during the K tile load (fp32-accurate).
// grid (8 m-tiles, 128 batches), 256 thr = 8 warps (4m x 2n).
// Per warp: m16 x n128 (16 n8-tiles, 64 fp32 accums).
// ============================================================
__global__ __launch_bounds__(256) void ftilde_mma_kernel(
    float* __restrict__ outP, float* __restrict__ outFt)
{
    __shared__ __align__(16) __nv_bfloat16 KhiS[64 * 40];   // pitch 40 (80B rows)
    __shared__ __align__(16) __nv_bfloat16 KloS[64 * 40];
    __shared__ __align__(16) __nv_bfloat16 GhiS[32 * 264];  // pitch 264 (528B rows)
    __shared__ __align__(16) __nv_bfloat16 GloS[32 * 264];

    int t = threadIdx.x, lane = t & 31, w = t >> 5;
    int wm = w & 3, wn = w >> 2;
    int it = blockIdx.x, b = blockIdx.y;
    int m0 = it * 64;
    const float* ub = g_u + b * NNq;
    const float* vb = g_v + b * NNq;

    float acc[16][4];
#pragma unroll
    for (int n = 0; n < 16; n++)
#pragma unroll
        for (int j = 0; j < 4; j++) acc[n][j] = 0.f;

    // per-thread load coords
    int lr = t >> 2, lseg = t & 3;                 // K tile: row, 8-elem segment
    float ui_r = __ldg(ub + m0 + lr);              // u for P row

    // ldmatrix base addresses (lane-dependent parts)
    unsigned aoff = (unsigned)((wm * 16 + (lane & 15)) * 80 + (lane >> 4) * 16);
    unsigned aHi = smaddr(KhiS) + aoff;
    unsigned aLo = smaddr(KloS) + aoff;
    unsigned boff = (unsigned)((lane & 15) * 528 + (wn * 128 + (lane >> 4) * 8) * 2);
    unsigned bHi = smaddr(GhiS) + boff;
    unsigned bLo = smaddr(GloS) + boff;

    for (int kc = 0; kc < NNq; kc += 32) {
        // ---- load K tiles (64x32 bf16 each) + fused P write ----
        {
            size_t gk = ((size_t)(b * NNq + m0 + lr)) * NNq + kc + lseg * 8;
            uint4 khi = *reinterpret_cast<const uint4*>(g_Kh + gk);
            uint4 klo = *reinterpret_cast<const uint4*>(g_Klo + gk);
            *reinterpret_cast<uint4*>(KhiS + lr * 40 + lseg * 8) = khi;
            *reinterpret_cast<uint4*>(KloS + lr * 40 + lseg * 8) = klo;

            const __nv_bfloat162* hp = reinterpret_cast<const __nv_bfloat162*>(&khi);
            const __nv_bfloat162* lp = reinterpret_cast<const __nv_bfloat162*>(&klo);
            float4 va = *reinterpret_cast<const float4*>(vb + kc + lseg * 8);
            float4 vb4 = *reinterpret_cast<const float4*>(vb + kc + lseg * 8 + 4);
            float kv[8];
#pragma unroll
            for (int j = 0; j < 4; j++) {
                float2 h2 = __bfloat1622float2(hp[j]);
                float2 l2 = __bfloat1622float2(lp[j]);
                kv[2 * j]     = h2.x + l2.x;
                kv[2 * j + 1] = h2.y + l2.y;
            }
            float4 p0, p1;
            p0.x = kv[0] * ui_r * va.x;  p0.y = kv[1] * ui_r * va.y;
            p0.z = kv[2] * ui_r * va.z;  p0.w = kv[3] * ui_r * va.w;
            p1.x = kv[4] * ui_r * vb4.x; p1.y = kv[5] * ui_r * vb4.y;
            p1.z = kv[6] * ui_r * vb4.z; p1.w = kv[7] * ui_r * vb4.w;
            *reinterpret_cast<float4*>(outP + gk)     = p0;
            *reinterpret_cast<float4*>(outP + gk + 4) = p1;
        }
        // ---- load G tiles (32x256 bf16 each) ----
#pragma unroll
        for (int j = 0; j < 4; j++) {
            int lin = t + 256 * j;
            int gr = lin >> 5, gc = (lin & 31) * 8;
            size_t gg = ((size_t)(b * NNq + kc + gr)) * FDq + gc;
            *reinterpret_cast<uint4*>(GhiS + gr * 264 + gc) =
                *reinterpret_cast<const uint4*>(g_Ghi + gg);
            *reinterpret_cast<uint4*>(GloS + gr * 264 + gc) =
                *reinterpret_cast<const uint4*>(g_Glo + gg);
        }
        __syncthreads();

        // ---- MMA over 2 k16 steps ----
#pragma unroll
        for (int ks = 0; ks < 2; ks++) {
            unsigned ahi0, ahi1, ahi2, ahi3, alo0, alo1, alo2, alo3;
            LDSM_X4(ahi0, ahi1, ahi2, ahi3, aHi + ks * 32);
            LDSM_X4(alo0, alo1, alo2, alo3, aLo + ks * 32);
#pragma unroll
            for (int n16 = 0; n16 < 8; n16++) {
                unsigned bo = ks * 16 * 528 + n16 * 32;
                unsigned bh0, bh1, bh2, bh3, bl0, bl1, bl2, bl3;
                LDSM_X4T(bh0, bh1, bh2, bh3, bHi + bo);
                LDSM_X4T(bl0, bl1, bl2, bl3, bLo + bo);
                MMA16816(acc[n16 * 2],     ahi0, ahi1, ahi2, ahi3, bh0, bh1);
                MMA16816(acc[n16 * 2],     ahi0, ahi1, ahi2, ahi3, bl0, bl1);
                MMA16816(acc[n16 * 2],     alo0, alo1, alo2, alo3, bh0, bh1);
                MMA16816(acc[n16 * 2 + 1], ahi0, ahi1, ahi2, ahi3, bh2, bh3);
                MMA16816(acc[n16 * 2 + 1], ahi0, ahi1, ahi2, ahi3, bl2, bl3);
                MMA16816(acc[n16 * 2 + 1], alo0, alo1, alo2, alo3, bh2, bh3);
            }
        }
        __syncthreads();
    }

    // ---- epilogue: scale by u, write Ft ----
    int r0 = m0 + wm * 16 + (lane >> 2), r1 = r0 + 8;
    float u0 = __ldg(ub + r0), u1 = __ldg(ub + r1);
    size_t ob0 = ((size_t)b * NNq + r0) * FDq;
    size_t ob1 = ((size_t)b * NNq + r1) * FDq;
#pragma unroll
    for (int nt = 0; nt < 16; nt++) {
        int col = wn * 128 + nt * 8 + (lane & 3) * 2;
        *reinterpret_cast<float2*>(outFt + ob0 + col) =
            make_float2(acc[nt][0] * u0, acc[nt][1] * u0);
        *reinterpret_cast<float2*>(outFt + ob1 + col) =
            make_float2(acc[nt][2] * u1, acc[nt][3] * u1);
    }
}

// ============================================================
extern "C" void kernel_launch(void* const* d_in, const int* in_sizes, int n_in,
                              void* d_out, int out_size)
{
    const float* S      = (const float*)d_in[0];
    const float* F      = (const float*)d_in[1];
    const float* W_s    = (const float*)d_in[2];
    const float* b_s    = (const float*)d_in[3];
    const float* g_s    = (const float*)d_in[4];
    const float* beta_s = (const float*)d_in[5];
    const float* W_f    = (const float*)d_in[6];
    const float* b_f    = (const float*)d_in[7];
    const float* g_f    = (const float*)d_in[8];
    const float* beta_f = (const float*)d_in[9];

    float* outP  = (float*)d_out;                               // [B,N,N]
    float* outFt = (float*)d_out + (size_t)BN * NNq * NNq;      // [B,N,FD]

    proj_kernel<<<(BN * NNq) / 64, 256>>>(S, W_s, b_s, g_s, beta_s, 0);
    proj_kernel<<<(BN * NNq) / 64, 256>>>(F, W_f, b_f, g_f, beta_f, 1);

    dim3 gcos(NNq / 128, NNq / 128, BN);
    cosk_kernel<<<gcos, 256>>>();

    sinkhorn_kernel<<<BN, 1024>>>();

    gprep_kernel<<<(BN * NNq * FDq / 4) / 256, 256>>>(F);

    dim3 gft(NNq / 64, BN);
    ftilde_mma_kernel<<<gft, 256>>>(outP, outFt);
}

// round 16
// speedup vs baseline: 3.1521x; 1.1400x over previous
#include <cuda_runtime.h>
#include <cuda_bf16.h>

#define BN 128
#define NNq 512
#define PDq 128
#define SDq 256
#define FDq 256
#define NITERS 30

typedef unsigned long long ull;

__device__ __nv_bfloat16 g_SpH[BN * NNq * PDq];
__device__ __nv_bfloat16 g_SpL[BN * NNq * PDq];
__device__ __nv_bfloat16 g_FpH[BN * NNq * PDq];
__device__ __nv_bfloat16 g_FpL[BN * NNq * PDq];
__device__ __nv_bfloat16 g_Kh [(size_t)BN * NNq * NNq];   // K hi (bf16 rn)
__device__ __nv_bfloat16 g_Klo[(size_t)BN * NNq * NNq];   // K - float(Khi)
__device__ __nv_bfloat16 g_Ghi[(size_t)BN * NNq * FDq];   // (v*F) hi
__device__ __nv_bfloat16 g_Glo[(size_t)BN * NNq * FDq];   // (v*F) lo
__device__ float g_u[BN * NNq];
__device__ float g_v[BN * NNq];

__device__ __forceinline__ ull pack2(float x, float y) {
    ull r;
    asm("mov.b64 %0, {%1, %2};" : "=l"(r) : "f"(x), "f"(y));
    return r;
}
__device__ __forceinline__ void fma2(ull& d, ull a, ull b) {
    asm("fma.rn.f32x2 %0, %1, %2, %0;" : "+l"(d) : "l"(a), "l"(b));
}
__device__ __forceinline__ float2 unpack2(ull v) {
    float lo, hi;
    asm("mov.b64 {%0, %1}, %2;" : "=f"(lo), "=f"(hi) : "l"(v));
    return make_float2(lo, hi);
}
__device__ __forceinline__ unsigned smaddr(const void* p) {
    return (unsigned)__cvta_generic_to_shared(p);
}

#define LDSM_X4(r0, r1, r2, r3, a) \
    asm volatile("ldmatrix.sync.aligned.m8n8.x4.shared.b16 {%0,%1,%2,%3},[%4];" \
                 : "=r"(r0), "=r"(r1), "=r"(r2), "=r"(r3) : "r"(a))
#define LDSM_X4T(r0, r1, r2, r3, a) \
    asm volatile("ldmatrix.sync.aligned.m8n8.x4.trans.shared.b16 {%0,%1,%2,%3},[%4];" \
                 : "=r"(r0), "=r"(r1), "=r"(r2), "=r"(r3) : "r"(a))
#define MMA16816(c, a0, a1, a2, a3, b0, b1) \
    asm volatile("mma.sync.aligned.m16n8k16.row.col.f32.bf16.bf16.f32 " \
                 "{%0,%1,%2,%3},{%4,%5,%6,%7},{%8,%9},{%0,%1,%2,%3};" \
                 : "+f"((c)[0]), "+f"((c)[1]), "+f"((c)[2]), "+f"((c)[3]) \
                 : "r"(a0), "r"(a1), "r"(a2), "r"(a3), "r"(b0), "r"(b1))

// ============================================================
// K1: H = X@W + b ; LayerNorm ; L2norm -> split bf16 Sp/Fp (hi+lo)
// ============================================================
__global__ __launch_bounds__(256) void proj_kernel(
    const float* __restrict__ X, const float* __restrict__ W,
    const float* __restrict__ bias, const float* __restrict__ gamma,
    const float* __restrict__ beta, int which)
{
    __shared__ __align__(16) char sraw[33280];
    ull*   Xs2 = reinterpret_cast<ull*>(sraw);            // [64][33] dup pairs
    float* Ws  = reinterpret_cast<float*>(sraw + 16896);  // [32][128]
    __nv_bfloat16* outH = which ? g_FpH : g_SpH;
    __nv_bfloat16* outL = which ? g_FpL : g_SpL;
    int t = threadIdx.x, tx = t & 15, ty = t >> 4;
    int row0 = blockIdx.x * 64;

    ull acc2[4][4];
#pragma unroll
    for (int i = 0; i < 4; i++)
#pragma unroll
        for (int j = 0; j < 4; j++) acc2[i][j] = 0ull;

    for (int kc = 0; kc < SDq; kc += 32) {
#pragma unroll
        for (int l = 0; l < 2; l++) {
            int r = t >> 2, c4 = (t & 3) * 4 + 16 * l;
            float4 v = *reinterpret_cast<const float4*>(X + (size_t)(row0 + r) * SDq + kc + c4);
            Xs2[r * 33 + c4 + 0] = pack2(v.x, v.x);
            Xs2[r * 33 + c4 + 1] = pack2(v.y, v.y);
            Xs2[r * 33 + c4 + 2] = pack2(v.z, v.z);
            Xs2[r * 33 + c4 + 3] = pack2(v.w, v.w);
        }
#pragma unroll
        for (int l = 0; l < 4; l++) {
            int r = (t >> 5) + 8 * l, c4 = (t & 31) * 4;
            *reinterpret_cast<float4*>(Ws + r * 128 + c4) =
                *reinterpret_cast<const float4*>(W + (size_t)(kc + r) * PDq + c4);
        }
        __syncthreads();
#pragma unroll
        for (int k = 0; k < 32; k++) {
            ull a2[4], w2[4];
#pragma unroll
            for (int i = 0; i < 4; i++) a2[i] = Xs2[(ty * 4 + i) * 33 + k];
#pragma unroll
            for (int h = 0; h < 4; h++)
                w2[h] = *reinterpret_cast<const ull*>(Ws + k * 128 + tx * 2 + 32 * h);
#pragma unroll
            for (int i = 0; i < 4; i++)
#pragma unroll
                for (int h = 0; h < 4; h++) fma2(acc2[i][h], a2[i], w2[h]);
        }
        __syncthreads();
    }

    float* Hs = reinterpret_cast<float*>(sraw);  // [64][128]
#pragma unroll
    for (int i = 0; i < 4; i++) {
        int r = ty * 4 + i;
#pragma unroll
        for (int h = 0; h < 4; h++) {
            float2 p = unpack2(acc2[i][h]);
            int c = tx * 2 + 32 * h;
            Hs[r * 128 + c]     = p.x + __ldg(bias + c);
            Hs[r * 128 + c + 1] = p.y + __ldg(bias + c + 1);
        }
    }
    __syncthreads();

    int w = t >> 5, lane = t & 31;
    for (int q = 0; q < 8; q++) {
        int r = w * 8 + q;
        float h[4];
#pragma unroll
        for (int j = 0; j < 4; j++) h[j] = Hs[r * 128 + lane + 32 * j];
        float s = h[0] + h[1] + h[2] + h[3];
#pragma unroll
        for (int o = 16; o; o >>= 1) s += __shfl_xor_sync(0xffffffffu, s, o);
        float mu = s * (1.0f / 128.0f);
        float vsm = 0.f;
#pragma unroll
        for (int j = 0; j < 4; j++) { float d = h[j] - mu; vsm += d * d; }
#pragma unroll
        for (int o = 16; o; o >>= 1) vsm += __shfl_xor_sync(0xffffffffu, vsm, o);
        float rstd = rsqrtf(vsm * (1.0f / 128.0f) + 1e-5f);
        float y[4]; float ss = 0.f;
#pragma unroll
        for (int j = 0; j < 4; j++) {
            int c = lane + 32 * j;
            y[j] = (h[j] - mu) * rstd * __ldg(gamma + c) + __ldg(beta + c);
            ss += y[j] * y[j];
        }
#pragma unroll
        for (int o = 16; o; o >>= 1) ss += __shfl_xor_sync(0xffffffffu, ss, o);
        float inv = 1.0f / fmaxf(sqrtf(ss), 1e-12f);
        size_t ob = (size_t)(row0 + r) * PDq;
#pragma unroll
        for (int j = 0; j < 4; j++) {
            float val = y[j] * inv;
            __nv_bfloat16 hi = __float2bfloat16_rn(val);
            __nv_bfloat16 lo = __float2bfloat16_rn(val - __bfloat162float(hi));
            outH[ob + lane + 32 * j] = hi;
            outL[ob + lane + 32 * j] = lo;
        }
    }
}

// ============================================================
// K2: tensor-core cosK.  cos = Sp@Fp^T via bf16x3:
//     Shi@Fhi + Shi@Flo + Slo@Fhi  (mma m16n8k16).
//     K = exp(-10*clip(1-cos,0,2)) -> split Kh + Klo.
// CTA: m64 x n128, 8 warps (4m x 2n), warp m16 x n64.
// A from [m][k] non-trans ldmatrix; B from [n][k] non-trans ldmatrix
//   (frag pairs {r0,r2} for n0-7, {r1,r3} for n8-15).
// ============================================================
__global__ __launch_bounds__(256) void cosk_mma_kernel()
{
    __shared__ __align__(16) __nv_bfloat16 AhS[64 * 40];    // pitch 40 bf16 (80B)
    __shared__ __align__(16) __nv_bfloat16 AlS[64 * 40];
    __shared__ __align__(16) __nv_bfloat16 BhS[128 * 40];
    __shared__ __align__(16) __nv_bfloat16 BlS[128 * 40];

    int t = threadIdx.x, lane = t & 31, w = t >> 5;
    int wm = w & 3, wn = w >> 2;
    int jt = blockIdx.x, it = blockIdx.y, b = blockIdx.z;
    int m0 = it * 64, n0 = jt * 128;

    float acc[8][4];
#pragma unroll
    for (int g = 0; g < 8; g++)
#pragma unroll
        for (int j = 0; j < 4; j++) acc[g][j] = 0.f;

    int lr = t >> 2, ls = (t & 3) * 8;   // A row / k-seg, B row / k-seg

    unsigned aoff = (unsigned)((wm * 16 + (lane & 15)) * 80 + (lane >> 4) * 16);
    unsigned aH = smaddr(AhS) + aoff;
    unsigned aL = smaddr(AlS) + aoff;
    unsigned boff = (unsigned)((wn * 64 + (lane & 15)) * 80 + (lane >> 4) * 16);
    unsigned bH = smaddr(BhS) + boff;
    unsigned bL = smaddr(BlS) + boff;

    for (int kc = 0; kc < PDq; kc += 32) {
        // A tiles: 64 x 32 (hi, lo)
        {
            size_t ga = ((size_t)(b * NNq + m0 + lr)) * PDq + kc + ls;
            *reinterpret_cast<uint4*>(AhS + lr * 40 + ls) =
                *reinterpret_cast<const uint4*>(g_SpH + ga);
            *reinterpret_cast<uint4*>(AlS + lr * 40 + ls) =
                *reinterpret_cast<const uint4*>(g_SpL + ga);
        }
        // B tiles: 128 x 32 (hi, lo)
#pragma unroll
        for (int j = 0; j < 2; j++) {
            int br = lr + 64 * j;
            size_t gb = ((size_t)(b * NNq + n0 + br)) * PDq + kc + ls;
            *reinterpret_cast<uint4*>(BhS + br * 40 + ls) =
                *reinterpret_cast<const uint4*>(g_FpH + gb);
            *reinterpret_cast<uint4*>(BlS + br * 40 + ls) =
                *reinterpret_cast<const uint4*>(g_FpL + gb);
        }
        __syncthreads();

#pragma unroll
        for (int ks = 0; ks < 2; ks++) {
            unsigned ah0, ah1, ah2, ah3, al0, al1, al2, al3;
            LDSM_X4(ah0, ah1, ah2, ah3, aH + ks * 32);
            LDSM_X4(al0, al1, al2, al3, aL + ks * 32);
#pragma unroll
            for (int g = 0; g < 4; g++) {            // n16 groups in warp's n64
                unsigned go = (unsigned)(g * 16 * 80 + ks * 32);
                unsigned bh0, bh1, bh2, bh3, bl0, bl1, bl2, bl3;
                LDSM_X4(bh0, bh1, bh2, bh3, bH + go);
                LDSM_X4(bl0, bl1, bl2, bl3, bL + go);
                // n0-7 frag {x0,x2}; n8-15 frag {x1,x3}
                MMA16816(acc[g * 2],     ah0, ah1, ah2, ah3, bh0, bh2);
                MMA16816(acc[g * 2],     ah0, ah1, ah2, ah3, bl0, bl2);
                MMA16816(acc[g * 2],     al0, al1, al2, al3, bh0, bh2);
                MMA16816(acc[g * 2 + 1], ah0, ah1, ah2, ah3, bh1, bh3);
                MMA16816(acc[g * 2 + 1], ah0, ah1, ah2, ah3, bl1, bl3);
                MMA16816(acc[g * 2 + 1], al0, al1, al2, al3, bh1, bh3);
            }
        }
        __syncthreads();
    }

    // epilogue: K = exp(-10*clip(1-cos,0,2)), split hi/lo bf16
    int r0 = m0 + wm * 16 + (lane >> 2), r1 = r0 + 8;
#pragma unroll
    for (int g = 0; g < 8; g++) {
        int col = n0 + wn * 64 + g * 8 + (lane & 3) * 2;
#pragma unroll
        for (int hrow = 0; hrow < 2; hrow++) {
            int row = hrow ? r1 : r0;
            float cx = acc[g][hrow * 2], cy = acc[g][hrow * 2 + 1];
            float ex = __expf(-10.0f * fminf(fmaxf(1.0f - cx, 0.f), 2.f));
            float ey = __expf(-10.0f * fminf(fmaxf(1.0f - cy, 0.f), 2.f));
            __nv_bfloat162 hi2 = __floats2bfloat162_rn(ex, ey);
            __nv_bfloat162 lo2 = __floats2bfloat162_rn(
                ex - __bfloat162float(hi2.x), ey - __bfloat162float(hi2.y));
            size_t idx = ((size_t)b * NNq + row) * NNq + col;
            *reinterpret_cast<__nv_bfloat162*>(g_Kh  + idx) = hi2;
            *reinterpret_cast<__nv_bfloat162*>(g_Klo + idx) = lo2;
        }
    }
}

// ============================================================
// K3: Sinkhorn 30 iters on bf16 Khi (L2-resident). Unchanged.
// ============================================================
__global__ __launch_bounds__(1024) void sinkhorn_kernel()
{
    __shared__ float vs[512];
    __shared__ float us[512];
    __shared__ float part[16 * 512];
    int t = threadIdx.x, w = t >> 5, l = t & 31, b = blockIdx.x;
    const uint4* Kb = reinterpret_cast<const uint4*>(g_Kh + (size_t)b * NNq * NNq);

    if (t < 512) vs[t] = 1.0f;
    __syncthreads();
    const float rr = 1.0f / 512.0f;

    for (int iter = 0; iter < NITERS; ++iter) {
        float acc[16];
#pragma unroll
        for (int i = 0; i < 16; i++) acc[i] = 0.f;

        float va[16];
#pragma unroll
        for (int h = 0; h < 2; h++) {
            float4 v0 = *reinterpret_cast<const float4*>(vs + 256 * h + 8 * l);
            float4 v1 = *reinterpret_cast<const float4*>(vs + 256 * h + 8 * l + 4);
            va[h * 8 + 0] = v0.x; va[h * 8 + 1] = v0.y;
            va[h * 8 + 2] = v0.z; va[h * 8 + 3] = v0.w;
            va[h * 8 + 4] = v1.x; va[h * 8 + 5] = v1.y;
            va[h * 8 + 6] = v1.z; va[h * 8 + 7] = v1.w;
        }

#pragma unroll 1
        for (int row = w * 16; row < w * 16 + 16; ++row) {
            uint4 k0 = Kb[(size_t)row * 64 + l];
            uint4 k1 = Kb[(size_t)row * 64 + 32 + l];
            float kf[16];
            kf[0]  = __uint_as_float(k0.x << 16);
            kf[1]  = __uint_as_float(k0.x & 0xffff0000u);
            kf[2]  = __uint_as_float(k0.y << 16);
            kf[3]  = __uint_as_float(k0.y & 0xffff0000u);
            kf[4]  = __uint_as_float(k0.z << 16);
            kf[5]  = __uint_as_float(k0.z & 0xffff0000u);
            kf[6]  = __uint_as_float(k0.w << 16);
            kf[7]  = __uint_as_float(k0.w & 0xffff0000u);
            kf[8]  = __uint_as_float(k1.x << 16);
            kf[9]  = __uint_as_float(k1.x & 0xffff0000u);
            kf[10] = __uint_as_float(k1.y << 16);
            kf[11] = __uint_as_float(k1.y & 0xffff0000u);
            kf[12] = __uint_as_float(k1.z << 16);
            kf[13] = __uint_as_float(k1.z & 0xffff0000u);
            kf[14] = __uint_as_float(k1.w << 16);
            kf[15] = __uint_as_float(k1.w & 0xffff0000u);

            float s = 0.f;
#pragma unroll
            for (int i = 0; i < 16; i++) s += kf[i] * va[i];
#pragma unroll
            for (int o = 16; o; o >>= 1) s += __shfl_xor_sync(0xffffffffu, s, o);
            float u = rr / (s + 1e-8f);
            if (l == 0) us[row] = u;
#pragma unroll
            for (int i = 0; i < 16; i++) acc[i] += u * kf[i];
        }

        if (w >= 16) {
            int wb = (w - 16) * 512;
#pragma unroll
            for (int h = 0; h < 2; h++) {
                *reinterpret_cast<float4*>(part + wb + 256 * h + 8 * l) =
                    make_float4(acc[h * 8 + 0], acc[h * 8 + 1], acc[h * 8 + 2], acc[h * 8 + 3]);
                *reinterpret_cast<float4*>(part + wb + 256 * h + 8 * l + 4) =
                    make_float4(acc[h * 8 + 4], acc[h * 8 + 5], acc[h * 8 + 6], acc[h * 8 + 7]);
            }
        }
        __syncthreads();
        if (w < 16) {
            int wb = w * 512;
#pragma unroll
            for (int h = 0; h < 2; h++) {
                float4 p0 = *reinterpret_cast<const float4*>(part + wb + 256 * h + 8 * l);
                float4 p1 = *reinterpret_cast<const float4*>(part + wb + 256 * h + 8 * l + 4);
                p0.x += acc[h * 8 + 0]; p0.y += acc[h * 8 + 1];
                p0.z += acc[h * 8 + 2]; p0.w += acc[h * 8 + 3];
                p1.x += acc[h * 8 + 4]; p1.y += acc[h * 8 + 5];
                p1.z += acc[h * 8 + 6]; p1.w += acc[h * 8 + 7];
                *reinterpret_cast<float4*>(part + wb + 256 * h + 8 * l) = p0;
                *reinterpret_cast<float4*>(part + wb + 256 * h + 8 * l + 4) = p1;
            }
        }
        __syncthreads();

        if (t < 512) {
            float kt = 0.f;
#pragma unroll
            for (int ww = 0; ww < 16; ++ww) kt += part[ww * 512 + t];
            float v = rr / (kt + 1e-8f);
            vs[t] = fminf(fmaxf(v, 1e-8f), 1e8f);
        }
        __syncthreads();
    }
    if (t < 512) {
        g_u[b * NNq + t] = fminf(fmaxf(us[t], 1e-8f), 1e8f);
        g_v[b * NNq + t] = vs[t];
    }
}

// ============================================================
// K3b: G = v (*) F  split into bf16 hi/lo  (g_Ghi, g_Glo)
// ============================================================
__global__ __launch_bounds__(256) void gprep_kernel(const float* __restrict__ F)
{
    int idx = blockIdx.x * 256 + threadIdx.x;        // one float4 per thread
    int b = idx >> 15;                               // 32768 quads per batch
    int rem = idx & 32767;
    int k = rem >> 6;
    int c4 = (rem & 63) * 4;
    float vsc = __ldg(g_v + b * NNq + k);
    size_t base = ((size_t)b * NNq + k) * FDq + c4;
    float4 f4 = *reinterpret_cast<const float4*>(F + base);
    float gx = f4.x * vsc, gy = f4.y * vsc, gz = f4.z * vsc, gw = f4.w * vsc;
    __nv_bfloat162 h0 = __floats2bfloat162_rn(gx, gy);
    __nv_bfloat162 h1 = __floats2bfloat162_rn(gz, gw);
    __nv_bfloat162 l0 = __floats2bfloat162_rn(gx - __bfloat162float(h0.x),
                                              gy - __bfloat162float(h0.y));
    __nv_bfloat162 l1 = __floats2bfloat162_rn(gz - __bfloat162float(h1.x),
                                              gw - __bfloat162float(h1.y));
    uint2 hh, ll;
    hh.x = *reinterpret_cast<unsigned*>(&h0); hh.y = *reinterpret_cast<unsigned*>(&h1);
    ll.x = *reinterpret_cast<unsigned*>(&l0); ll.y = *reinterpret_cast<unsigned*>(&l1);
    *reinterpret_cast<uint2*>(g_Ghi + base) = hh;
    *reinterpret_cast<uint2*>(g_Glo + base) = ll;
}

// ============================================================
// K4: tensor-core ftilde (unchanged from R14).
// ============================================================
__global__ __launch_bounds__(256) void ftilde_mma_kernel(
    float* __restrict__ outP, float* __restrict__ outFt)
{
    __shared__ __align__(16) __nv_bfloat16 KhiS[64 * 40];   // pitch 40 (80B rows)
    __shared__ __align__(16) __nv_bfloat16 KloS[64 * 40];
    __shared__ __align__(16) __nv_bfloat16 GhiS[32 * 264];  // pitch 264 (528B rows)
    __shared__ __align__(16) __nv_bfloat16 GloS[32 * 264];

    int t = threadIdx.x, lane = t & 31, w = t >> 5;
    int wm = w & 3, wn = w >> 2;
    int it = blockIdx.x, b = blockIdx.y;
    int m0 = it * 64;
    const float* ub = g_u + b * NNq;
    const float* vb = g_v + b * NNq;

    float acc[16][4];
#pragma unroll
    for (int n = 0; n < 16; n++)
#pragma unroll
        for (int j = 0; j < 4; j++) acc[n][j] = 0.f;

    int lr = t >> 2, lseg = t & 3;
    float ui_r = __ldg(ub + m0 + lr);

    unsigned aoff = (unsigned)((wm * 16 + (lane & 15)) * 80 + (lane >> 4) * 16);
    unsigned aHi = smaddr(KhiS) + aoff;
    unsigned aLo = smaddr(KloS) + aoff;
    unsigned boff = (unsigned)((lane & 15) * 528 + (wn * 128 + (lane >> 4) * 8) * 2);
    unsigned bHi = smaddr(GhiS) + boff;
    unsigned bLo = smaddr(GloS) + boff;

    for (int kc = 0; kc < NNq; kc += 32) {
        {
            size_t gk = ((size_t)(b * NNq + m0 + lr)) * NNq + kc + lseg * 8;
            uint4 khi = *reinterpret_cast<const uint4*>(g_Kh + gk);
            uint4 klo = *reinterpret_cast<const uint4*>(g_Klo + gk);
            *reinterpret_cast<uint4*>(KhiS + lr * 40 + lseg * 8) = khi;
            *reinterpret_cast<uint4*>(KloS + lr * 40 + lseg * 8) = klo;

            const __nv_bfloat162* hp = reinterpret_cast<const __nv_bfloat162*>(&khi);
            const __nv_bfloat162* lp = reinterpret_cast<const __nv_bfloat162*>(&klo);
            float4 va = *reinterpret_cast<const float4*>(vb + kc + lseg * 8);
            float4 vb4 = *reinterpret_cast<const float4*>(vb + kc + lseg * 8 + 4);
            float kv[8];
#pragma unroll
            for (int j = 0; j < 4; j++) {
                float2 h2 = __bfloat1622float2(hp[j]);
                float2 l2 = __bfloat1622float2(lp[j]);
                kv[2 * j]     = h2.x + l2.x;
                kv[2 * j + 1] = h2.y + l2.y;
            }
            float4 p0, p1;
            p0.x = kv[0] * ui_r * va.x;  p0.y = kv[1] * ui_r * va.y;
            p0.z = kv[2] * ui_r * va.z;  p0.w = kv[3] * ui_r * va.w;
            p1.x = kv[4] * ui_r * vb4.x; p1.y = kv[5] * ui_r * vb4.y;
            p1.z = kv[6] * ui_r * vb4.z; p1.w = kv[7] * ui_r * vb4.w;
            *reinterpret_cast<float4*>(outP + gk)     = p0;
            *reinterpret_cast<float4*>(outP + gk + 4) = p1;
        }
#pragma unroll
        for (int j = 0; j < 4; j++) {
            int lin = t + 256 * j;
            int gr = lin >> 5, gc = (lin & 31) * 8;
            size_t gg = ((size_t)(b * NNq + kc + gr)) * FDq + gc;
            *reinterpret_cast<uint4*>(GhiS + gr * 264 + gc) =
                *reinterpret_cast<const uint4*>(g_Ghi + gg);
            *reinterpret_cast<uint4*>(GloS + gr * 264 + gc) =
                *reinterpret_cast<const uint4*>(g_Glo + gg);
        }
        __syncthreads();

#pragma unroll
        for (int ks = 0; ks < 2; ks++) {
            unsigned ahi0, ahi1, ahi2, ahi3, alo0, alo1, alo2, alo3;
            LDSM_X4(ahi0, ahi1, ahi2, ahi3, aHi + ks * 32);
            LDSM_X4(alo0, alo1, alo2, alo3, aLo + ks * 32);
#pragma unroll
            for (int n16 = 0; n16 < 8; n16++) {
                unsigned bo = ks * 16 * 528 + n16 * 32;
                unsigned bh0, bh1, bh2, bh3, bl0, bl1, bl2, bl3;
                LDSM_X4T(bh0, bh1, bh2, bh3, bHi + bo);
                LDSM_X4T(bl0, bl1, bl2, bl3, bLo + bo);
                MMA16816(acc[n16 * 2],     ahi0, ahi1, ahi2, ahi3, bh0, bh1);
                MMA16816(acc[n16 * 2],     ahi0, ahi1, ahi2, ahi3, bl0, bl1);
                MMA16816(acc[n16 * 2],     alo0, alo1, alo2, alo3, bh0, bh1);
                MMA16816(acc[n16 * 2 + 1], ahi0, ahi1, ahi2, ahi3, bh2, bh3);
                MMA16816(acc[n16 * 2 + 1], ahi0, ahi1, ahi2, ahi3, bl2, bl3);
                MMA16816(acc[n16 * 2 + 1], alo0, alo1, alo2, alo3, bh2, bh3);
            }
        }
        __syncthreads();
    }

    int r0 = m0 + wm * 16 + (lane >> 2), r1 = r0 + 8;
    float u0 = __ldg(ub + r0), u1 = __ldg(ub + r1);
    size_t ob0 = ((size_t)b * NNq + r0) * FDq;
    size_t ob1 = ((size_t)b * NNq + r1) * FDq;
#pragma unroll
    for (int nt = 0; nt < 16; nt++) {
        int col = wn * 128 + nt * 8 + (lane & 3) * 2;
        *reinterpret_cast<float2*>(outFt + ob0 + col) =
            make_float2(acc[nt][0] * u0, acc[nt][1] * u0);
        *reinterpret_cast<float2*>(outFt + ob1 + col) =
            make_float2(acc[nt][2] * u1, acc[nt][3] * u1);
    }
}

// ============================================================
extern "C" void kernel_launch(void* const* d_in, const int* in_sizes, int n_in,
                              void* d_out, int out_size)
{
    const float* S      = (const float*)d_in[0];
    const float* F      = (const float*)d_in[1];
    const float* W_s    = (const float*)d_in[2];
    const float* b_s    = (const float*)d_in[3];
    const float* g_s    = (const float*)d_in[4];
    const float* beta_s = (const float*)d_in[5];
    const float* W_f    = (const float*)d_in[6];
    const float* b_f    = (const float*)d_in[7];
    const float* g_f    = (const float*)d_in[8];
    const float* beta_f = (const float*)d_in[9];

    float* outP  = (float*)d_out;                               // [B,N,N]
    float* outFt = (float*)d_out + (size_t)BN * NNq * NNq;      // [B,N,FD]

    proj_kernel<<<(BN * NNq) / 64, 256>>>(S, W_s, b_s, g_s, beta_s, 0);
    proj_kernel<<<(BN * NNq) / 64, 256>>>(F, W_f, b_f, g_f, beta_f, 1);

    dim3 gcos(NNq / 128, NNq / 64, BN);
    cosk_mma_kernel<<<gcos, 256>>>();

    sinkhorn_kernel<<<BN, 1024>>>();

    gprep_kernel<<<(BN * NNq * FDq / 4) / 256, 256>>>(F);

    dim3 gft(NNq / 64, BN);
    ftilde_mma_kernel<<<gft, 256>>>(outP, outFt);
}